// round 11
// baseline (speedup 1.0000x reference)
#include <cuda_runtime.h>
#include <cuda_bf16.h>
#include <cstdint>

#define BATCH 2
#define S_LEN 2048
#define ED    1024
#define NH    16
#define HD    64
#define HALF_W 256
#define MROWS (BATCH * S_LEN)   // 4096

#if defined(__CUDA_ARCH_FEAT_SM103_ALL) || defined(__CUDA_ARCH_FEAT_SM100_ALL)
#define HAS_TCGEN05 1
#else
#define HAS_TCGEN05 0
#endif

// ---------------------------------------------------------------------------
// Scratch (device globals)
// ---------------------------------------------------------------------------
__device__ __nv_bfloat16 g_xhi[MROWS * ED];
__device__ __nv_bfloat16 g_xlo[MROWS * ED];
__device__ __nv_bfloat16 g_whi[4 * ED * ED];   // transposed weights [z][n][k]
__device__ __nv_bfloat16 g_wlo[4 * ED * ED];
__device__ __nv_bfloat16 g_qkvh[3 * MROWS * ED];  // Q,K: [b,h,s,d]; V: [b,h,d,s]
__device__ __nv_bfloat16 g_qkvl[3 * MROWS * ED];
__device__ __nv_bfloat16 g_ahi[MROWS * ED];
__device__ __nv_bfloat16 g_alo[MROWS * ED];

// ---------------------------------------------------------------------------
// PTX helpers
// ---------------------------------------------------------------------------
__device__ __forceinline__ uint32_t smem_to_u32(const void* p) {
    uint32_t a;
    asm("{ .reg .u64 t; cvta.to.shared.u64 t, %1; cvt.u32.u64 %0, t; }" : "=r"(a) : "l"(p));
    return a;
}
#if HAS_TCGEN05
__device__ __forceinline__ uint32_t elect_one_pred() {
    uint32_t pred;
    asm volatile("{\n\t.reg .pred p;\n\telect.sync _|p, 0xFFFFFFFF;\n\tselp.b32 %0, 1, 0, p;\n\t}" : "=r"(pred));
    return pred;
}
#endif
#define MBARRIER_INIT(addr, cnt) \
    asm volatile("mbarrier.init.shared.b64 [%0], %1;" :: "r"((uint32_t)(addr)), "r"((uint32_t)(cnt)) : "memory")
#define MBARRIER_WAIT_PARITY(addr, par) do { \
    uint32_t _m = (uint32_t)(addr); uint32_t _p = (uint32_t)(par); uint32_t _d; \
    asm volatile("{\n\t.reg .pred p;\n\tmbarrier.try_wait.parity.acquire.cta.shared::cta.b64 p, [%1], %2;\n\tselp.b32 %0, 1, 0, p;\n\t}" \
        : "=r"(_d) : "r"(_m), "r"(_p) : "memory"); \
    if (!_d) { \
        asm volatile("{\n\t.reg .pred P1;\n\tWL_%=:\n\tmbarrier.try_wait.parity.acquire.cta.shared::cta.b64 P1, [%0], %1, 0x989680;\n\t@P1 bra.uni WD_%=;\n\tbra.uni WL_%=;\n\tWD_%=:\n\t}" \
            :: "r"(_m), "r"(_p) : "memory"); \
    } } while (0)
#define TCGEN05_ALLOC(sres, nc) \
    asm volatile("tcgen05.alloc.cta_group::1.sync.aligned.shared::cta.b32 [%0], %1;" :: "r"((uint32_t)(sres)), "r"((uint32_t)(nc)) : "memory")
#define TCGEN05_DEALLOC(tm, nc) \
    asm volatile("tcgen05.dealloc.cta_group::1.sync.aligned.b32 %0, %1;" :: "r"(tm), "r"((uint32_t)(nc)))
#define TCGEN05_RELINQ() \
    asm volatile("tcgen05.relinquish_alloc_permit.cta_group::1.sync.aligned;")
#define TCGEN05_COMMIT(mb) \
    asm volatile("tcgen05.commit.cta_group::1.mbarrier::arrive::one.shared::cluster.b64 [%0];" :: "r"((uint32_t)(mb)) : "memory")
#define TCGEN05_FENCE_AFTER() asm volatile("tcgen05.fence::after_thread_sync;" ::: "memory")
#define TCGEN05_WAIT_LD() asm volatile("tcgen05.wait::ld.sync.aligned;" ::: "memory")
#define FENCE_PROXY_ASYNC() asm volatile("fence.proxy.async.shared::cta;" ::: "memory")
#define CP_ASYNC16(saddr, gptr) \
    asm volatile("cp.async.cg.shared.global [%0], [%1], 16;" :: "r"((uint32_t)(saddr)), "l"(gptr) : "memory")
#define CP_ASYNC_COMMIT() asm volatile("cp.async.commit_group;" ::: "memory")
#define CP_ASYNC_WAIT0()  asm volatile("cp.async.wait_group 0;" ::: "memory")
#define CP_ASYNC_WAIT1()  asm volatile("cp.async.wait_group 1;" ::: "memory")
#define STS128(addr, a, b, c, d) \
    asm volatile("st.shared.v4.b32 [%0], {%1, %2, %3, %4};" :: "r"((uint32_t)(addr)), "r"(a), "r"(b), "r"(c), "r"(d) : "memory")

#define TCGEN05_LD_X32(r, ta) \
    asm volatile("tcgen05.ld.sync.aligned.32x32b.x32.b32 " \
        "{%0, %1, %2, %3, %4, %5, %6, %7, %8, %9, %10, %11, %12, %13, %14, %15, " \
        " %16, %17, %18, %19, %20, %21, %22, %23, %24, %25, %26, %27, %28, %29, %30, %31}, [%32];" \
        : "=r"((r)[0]), "=r"((r)[1]), "=r"((r)[2]), "=r"((r)[3]), "=r"((r)[4]), "=r"((r)[5]), "=r"((r)[6]), "=r"((r)[7]), \
          "=r"((r)[8]), "=r"((r)[9]), "=r"((r)[10]), "=r"((r)[11]), "=r"((r)[12]), "=r"((r)[13]), "=r"((r)[14]), "=r"((r)[15]), \
          "=r"((r)[16]), "=r"((r)[17]), "=r"((r)[18]), "=r"((r)[19]), "=r"((r)[20]), "=r"((r)[21]), "=r"((r)[22]), "=r"((r)[23]), \
          "=r"((r)[24]), "=r"((r)[25]), "=r"((r)[26]), "=r"((r)[27]), "=r"((r)[28]), "=r"((r)[29]), "=r"((r)[30]), "=r"((r)[31]) \
        : "r"(ta))

// SMEM descriptors: K-major SW128 (128 B rows) and SW64 (64 B rows)
static constexpr uint64_t SMEM_DESC_BASE_SW128 =
    (uint64_t(2) << 61) | (uint64_t(1) << 46) | (uint64_t(64) << 32) | (uint64_t(1) << 16);
static constexpr uint64_t SMEM_DESC_BASE_SW64 =
    (uint64_t(4) << 61) | (uint64_t(1) << 46) | (uint64_t(32) << 32) | (uint64_t(1) << 16);
#define MAKE_SMEM_DESC(a)      (SMEM_DESC_BASE_SW128 | ((uint64_t)((a) >> 4) & 0x3FFF))
#define MAKE_SMEM_DESC_SW64(a) (SMEM_DESC_BASE_SW64  | ((uint64_t)((a) >> 4) & 0x3FFF))

// idesc: dtype F32 (bit4), atype BF16 (bit7), btype BF16 (bit10)
static constexpr uint32_t GEMM_IDESC = (8u << 24) | (16u << 17) | (1u << 10) | (1u << 7) | (1u << 4); // M128 N128
static constexpr uint32_t ATT_IDESC  = (8u << 24) | (8u << 17)  | (1u << 10) | (1u << 7) | (1u << 4); // M128 N64

#if HAS_TCGEN05
__device__ __forceinline__ void mma_bf16_ss(uint32_t d_tmem, uint64_t a_desc, uint64_t b_desc,
                                            uint32_t idesc, bool acc) {
    uint32_t en = acc ? 1u : 0u;
    asm volatile(
        "{\n\t.reg .pred p;\n\tsetp.ne.u32 p, %5, 0;\n\t"
        "tcgen05.mma.cta_group::1.kind::f16 [%0], %1, %2, %3, {%4, %4, %4, %4}, p;\n\t}"
        :: "r"(d_tmem), "l"(a_desc), "l"(b_desc), "r"(idesc), "r"(0u), "r"(en) : "memory");
}
#endif

__device__ __forceinline__ uint32_t pk2(float a, float b) {
    __nv_bfloat162 t = __floats2bfloat162_rn(a, b);
    return *reinterpret_cast<uint32_t*>(&t);
}
__device__ __forceinline__ float bfi(float v) {
    return __bfloat162float(__float2bfloat16(v));
}

// ---------------------------------------------------------------------------
// Merged prep kernel
// ---------------------------------------------------------------------------
__global__ __launch_bounds__(256) void prep_kernel(
    const float* __restrict__ x,
    const float* __restrict__ Wq, const float* __restrict__ Wk,
    const float* __restrict__ Wv, const float* __restrict__ Wo,
    __nv_bfloat16* __restrict__ xhi, __nv_bfloat16* __restrict__ xlo,
    __nv_bfloat16* __restrict__ whi, __nv_bfloat16* __restrict__ wlo)
{
    const int tid = threadIdx.x;
    if (blockIdx.x < 4096) {
        int i = blockIdx.x * 256 + tid;
        float4 v = reinterpret_cast<const float4*>(x)[i];
        float h0 = bfi(v.x), h1 = bfi(v.y), h2 = bfi(v.z), h3 = bfi(v.w);
        reinterpret_cast<uint2*>(xhi)[i] = make_uint2(pk2(v.x, v.y), pk2(v.z, v.w));
        reinterpret_cast<uint2*>(xlo)[i] = make_uint2(pk2(v.x - h0, v.y - h1), pk2(v.z - h2, v.w - h3));
    } else {
        __shared__ float ts[32][33];
        int bid = blockIdx.x - 4096;
        int z = bid >> 10;
        int rem = bid & 1023;
        int n0 = (rem & 31) * 32, k0 = (rem >> 5) * 32;
        const float* W = (z == 0) ? Wq : (z == 1) ? Wk : (z == 2) ? Wv : Wo;
        int tx = tid & 31, ty = tid >> 5;
        for (int r = ty; r < 32; r += 8)
            ts[r][tx] = W[(size_t)(k0 + r) * ED + n0 + tx];
        __syncthreads();
        size_t zoff = (size_t)z * ED * ED;
        for (int r = ty; r < 32; r += 8) {
            float v = ts[tx][r];
            float hf = bfi(v);
            size_t o = zoff + (size_t)(n0 + r) * ED + k0 + tx;
            whi[o] = __float2bfloat16(v);
            wlo[o] = __float2bfloat16(v - hf);
        }
    }
}

// ---------------------------------------------------------------------------
// bf16x3 tcgen05 GEMM — 128x128 tile, K-tile 32 (SW64), DOUBLE-buffered
// (2 x 32 KB), occ 2. load(t+1) overlaps MMA(t) via cp.async groups.
// smem: 0 ctrl | 1024 buf0 [Ahi|Alo|Bhi|Blo 8K each] | 33792 buf1 | 66560 end
// ---------------------------------------------------------------------------
#define GEMM_SMEM (1024 + 65536)

__global__ __launch_bounds__(256, 2) void gemm_bf16x3(
    const __nv_bfloat16* __restrict__ Ahi, const __nv_bfloat16* __restrict__ Alo,
    const __nv_bfloat16* __restrict__ Wh,  const __nv_bfloat16* __restrict__ Wl,
    const float* __restrict__ b0, const float* __restrict__ b1, const float* __restrict__ b2,
    float* __restrict__ cf, __nv_bfloat16* __restrict__ chi, __nv_bfloat16* __restrict__ clo,
    int mode)
{
    extern __shared__ char smc[];
    const int tid = threadIdx.x;
    const int wid = tid >> 5, lid = tid & 31;
    const int cRow = blockIdx.y;
    const int z    = mode ? (blockIdx.x >> 3) : 0;
    const int ncol = mode ? (blockIdx.x & 7) : blockIdx.x;

    const __nv_bfloat16* gA0 = Ahi + (size_t)cRow * 128 * ED;
    const __nv_bfloat16* gA1 = Alo + (size_t)cRow * 128 * ED;
    const __nv_bfloat16* gB0 = Wh + ((size_t)z * ED + ncol * 128) * ED;
    const __nv_bfloat16* gB1 = Wl + ((size_t)z * ED + ncol * 128) * ED;
    const float* bias = mode ? ((z == 0) ? b0 : (z == 1) ? b1 : b2) : b0;

#if HAS_TCGEN05
    const uint32_t smu = smem_to_u32(smc);
    const uint32_t bufu = smu + 1024;

    if (tid == 0) MBARRIER_INIT(smu + 8, 1);
    if (wid == 0) { TCGEN05_ALLOC(smu, 128); TCGEN05_RELINQ(); }
    __syncthreads();
    uint32_t tmem;
    asm volatile("ld.shared.b32 %0, [%1];" : "=r"(tmem) : "r"(smu));

    // Per-thread SW64 addressing: cc4 = tid&3 (16B chunk in 64B row),
    // rb = tid>>2 (0..63); thread covers rows rb and rb+64 per part.
    const int cc4 = tid & 3;
    const int rb = tid >> 2;
    uint32_t sw0, sw1;
    {
        uint32_t off0 = rb * 64 + cc4 * 16;
        uint32_t off1 = (rb + 64) * 64 + cc4 * 16;
        sw0 = off0 ^ ((off0 >> 3) & 0x30);
        sw1 = off1 ^ ((off1 >> 3) & 0x30);
    }
    const __nv_bfloat16* a0p = gA0 + (size_t)rb * ED + cc4 * 8;
    const __nv_bfloat16* a1p = gA1 + (size_t)rb * ED + cc4 * 8;
    const __nv_bfloat16* b0p = gB0 + (size_t)rb * ED + cc4 * 8;
    const __nv_bfloat16* b1p = gB1 + (size_t)rb * ED + cc4 * 8;

    auto load_tile = [&](int bsel, int k0e) {
        uint32_t bb = bufu + bsel * 32768;
        CP_ASYNC16(bb +         sw0, a0p + k0e);
        CP_ASYNC16(bb +         sw1, a0p + k0e + (size_t)64 * ED);
        CP_ASYNC16(bb +  8192 + sw0, a1p + k0e);
        CP_ASYNC16(bb +  8192 + sw1, a1p + k0e + (size_t)64 * ED);
        CP_ASYNC16(bb + 16384 + sw0, b0p + k0e);
        CP_ASYNC16(bb + 16384 + sw1, b0p + k0e + (size_t)64 * ED);
        CP_ASYNC16(bb + 24576 + sw0, b1p + k0e);
        CP_ASYNC16(bb + 24576 + sw1, b1p + k0e + (size_t)64 * ED);
        CP_ASYNC_COMMIT();
    };

    load_tile(0, 0);
    load_tile(1, 32);

    int ph = 0;
#pragma unroll 1
    for (int t = 0; t < 32; t++) {
        const int b = t & 1;
        CP_ASYNC_WAIT1();          // group t complete (t+1 may be in flight)
        FENCE_PROXY_ASYNC();
        __syncthreads();

        if (wid == 0) {
            if (elect_one_pred()) {
                uint32_t bb = bufu + b * 32768;
                uint64_t dAh = MAKE_SMEM_DESC_SW64(bb);
                uint64_t dAl = MAKE_SMEM_DESC_SW64(bb + 8192);
                uint64_t dBh = MAKE_SMEM_DESC_SW64(bb + 16384);
                uint64_t dBl = MAKE_SMEM_DESC_SW64(bb + 24576);
#pragma unroll
                for (int ks = 0; ks < 2; ks++) {
                    mma_bf16_ss(tmem, dAh + ks * 2, dBh + ks * 2, GEMM_IDESC, !(t == 0 && ks == 0));
                    mma_bf16_ss(tmem, dAh + ks * 2, dBl + ks * 2, GEMM_IDESC, true);
                    mma_bf16_ss(tmem, dAl + ks * 2, dBh + ks * 2, GEMM_IDESC, true);
                }
                TCGEN05_COMMIT(smu + 8);
            }
        }
        MBARRIER_WAIT_PARITY(smu + 8, ph); ph ^= 1;   // MMA reads of buf b done
        if (t + 2 < 32) load_tile(b, (t + 2) * 32);   // refill buf b
    }
    TCGEN05_FENCE_AFTER();

    // 8-warp epilogue: subpartition = wid&3 (lanes), column half = wid>>2.
    {
        const int sub = wid & 3;
        float* wsm = reinterpret_cast<float*>(smc + 1024) + wid * (32 * 33);
#pragma unroll 1
        for (int cc2 = 0; cc2 < 2; cc2++) {
            const int c = (wid >> 2) * 2 + cc2;
            uint32_t regs[32];
            TCGEN05_LD_X32(regs, tmem + c * 32);
            TCGEN05_WAIT_LD();
#pragma unroll
            for (int j = 0; j < 32; j++)
                wsm[lid * 33 + j] = __uint_as_float(regs[j]) + bias[ncol * 128 + c * 32 + j];
            __syncwarp();
            if (mode == 0) {
#pragma unroll
                for (int j = 0; j < 32; j++) {
                    int row = cRow * 128 + sub * 32 + j;
                    int col = ncol * 128 + c * 32 + lid;
                    cf[(size_t)row * ED + col] = wsm[j * 33 + lid];
                }
            } else if (z < 2) {
#pragma unroll
                for (int j = 0; j < 32; j++) {
                    float v = wsm[j * 33 + lid];
                    if (z == 0) v *= 0.125f;
                    int row = cRow * 128 + sub * 32 + j;
                    int col = ncol * 128 + c * 32 + lid;
                    int bb = row >> 11, s = row & 2047;
                    int hh = col >> 6, d = col & 63;
                    float hf = bfi(v);
                    size_t idx = (size_t)z * MROWS * ED + (((size_t)(bb * NH + hh)) * S_LEN + s) * HD + d;
                    chi[idx] = __float2bfloat16(v);
                    clo[idx] = __float2bfloat16(v - hf);
                }
            } else {
#pragma unroll
                for (int j = 0; j < 32; j++) {
                    float v = wsm[lid * 33 + j];
                    int row = cRow * 128 + sub * 32 + lid;
                    int col = ncol * 128 + c * 32 + j;
                    int bb = row >> 11, s = row & 2047;
                    int hh = col >> 6, d = col & 63;
                    float hf = bfi(v);
                    size_t idx = (size_t)2 * MROWS * ED + (((size_t)(bb * NH + hh)) * HD + d) * S_LEN + s;
                    chi[idx] = __float2bfloat16(v);
                    clo[idx] = __float2bfloat16(v - hf);
                }
            }
            __syncwarp();
        }
    }
    __syncthreads();
    if (wid == 0) TCGEN05_DEALLOC(tmem, 128);
#else
    // ---------------- FFMA fallback (never selected on GB300) ----------------
    float* As = reinterpret_cast<float*>(smc);
    float* Bs = As + 16 * 132;
    const int threadRow = tid / 16;
    const int threadCol = tid % 16;

    float acc[8][8];
#pragma unroll
    for (int i = 0; i < 8; i++)
#pragma unroll
        for (int j = 0; j < 8; j++) acc[i][j] = 0.0f;

    for (int k0 = 0; k0 < ED; k0 += 16) {
        for (int i = tid; i < 2048; i += 256) {
            int r = i >> 4, kk = i & 15;
            As[kk * 132 + r] = __bfloat162float(gA0[(size_t)r * ED + k0 + kk]) +
                               __bfloat162float(gA1[(size_t)r * ED + k0 + kk]);
            Bs[kk * 132 + r] = __bfloat162float(gB0[(size_t)r * ED + k0 + kk]) +
                               __bfloat162float(gB1[(size_t)r * ED + k0 + kk]);
        }
        __syncthreads();
#pragma unroll
        for (int kk = 0; kk < 16; kk++) {
            float regM[8], regN[8];
#pragma unroll
            for (int i = 0; i < 8; i++) regM[i] = As[kk * 132 + threadRow * 8 + i];
#pragma unroll
            for (int j = 0; j < 8; j++) regN[j] = Bs[kk * 132 + threadCol * 8 + j];
#pragma unroll
            for (int i = 0; i < 8; i++)
#pragma unroll
                for (int j = 0; j < 8; j++)
                    acc[i][j] = fmaf(regM[i], regN[j], acc[i][j]);
        }
        __syncthreads();
    }

#pragma unroll
    for (int i = 0; i < 8; i++) {
        int row = cRow * 128 + threadRow * 8 + i;
#pragma unroll
        for (int j = 0; j < 8; j++) {
            int col = ncol * 128 + threadCol * 8 + j;
            float v = acc[i][j] + bias[col];
            if (mode == 0) {
                cf[(size_t)row * ED + col] = v;
            } else {
                int bb = row >> 11, s = row & 2047;
                int hh = col >> 6, d = col & 63;
                if (z == 0) v *= 0.125f;
                size_t idx;
                if (z < 2) idx = (size_t)z * MROWS * ED + (((size_t)(bb * NH + hh)) * S_LEN + s) * HD + d;
                else       idx = (size_t)2 * MROWS * ED + (((size_t)(bb * NH + hh)) * HD + d) * S_LEN + s;
                float hf = bfi(v);
                chi[idx] = __float2bfloat16(v);
                clo[idx] = __float2bfloat16(v - hf);
            }
        }
    }
#endif
}

// ---------------------------------------------------------------------------
// Banded flash attention on tcgen05 — occ 2 (unchanged from round 10).
// smem map: 0 ctrl | 1024 Qhi 16K | 17408 Qlo 16K |
//           33792 Khi 8K | 41984 Klo 8K | 50176 Vhi 8K | 58368 Vlo 8K |
//           66560 Phi 16K | 82944 Plo 16K | total 99328
// ---------------------------------------------------------------------------
#define ATT_SMEM 99328

__global__ __launch_bounds__(128, 2) void attn_tc_kernel(
    const __nv_bfloat16* __restrict__ qkvh, const __nv_bfloat16* __restrict__ qkvl,
    __nv_bfloat16* __restrict__ Ohi, __nv_bfloat16* __restrict__ Olo)
{
    extern __shared__ char smc[];
    const int tid = threadIdx.x;
    const int wid = tid >> 5, lid = tid & 31;
    const int b = blockIdx.z, h = blockIdx.y;
    const int q0 = blockIdx.x * 128;
    const size_t bh = (size_t)(b * NH + h);

    const __nv_bfloat16* Qh = qkvh + bh * S_LEN * HD;
    const __nv_bfloat16* Ql = qkvl + bh * S_LEN * HD;
    const __nv_bfloat16* Kh = qkvh + (size_t)MROWS * ED + bh * S_LEN * HD;
    const __nv_bfloat16* Kl = qkvl + (size_t)MROWS * ED + bh * S_LEN * HD;
    const __nv_bfloat16* Vh = qkvh + (size_t)2 * MROWS * ED + bh * HD * S_LEN;
    const __nv_bfloat16* Vl = qkvl + (size_t)2 * MROWS * ED + bh * HD * S_LEN;

    const int gq = q0 + wid * 32 + lid;

#if HAS_TCGEN05
    const uint32_t smu = smem_to_u32(smc);

    if (tid == 0) MBARRIER_INIT(smu + 8, 1);
    if (wid == 0) { TCGEN05_ALLOC(smu, 128); TCGEN05_RELINQ(); }
    __syncthreads();
    uint32_t tmem;
    asm volatile("ld.shared.b32 %0, [%1];" : "=r"(tmem) : "r"(smu));

    // Load Q hi/lo (128 rows x 64 bf16, SW128)
#pragma unroll
    for (int i = 0; i < 16; i++) {
        int idx = i * 128 + tid;
        int arr = idx >> 10;
        int r = (idx >> 3) & 127, c = idx & 7;
        const __nv_bfloat16* src = arr ? Ql : Qh;
        uint32_t off = r * 128 + c * 16;
        CP_ASYNC16(smu + 1024 + arr * 16384 + (off ^ ((off >> 3) & 0x70)),
                   src + (size_t)(q0 + r) * HD + c * 8);
    }
    CP_ASYNC_COMMIT();

    const int it0 = (q0 < 256) ? ((256 - q0) >> 6) : 0;
    const int it1raw = (2240 - q0) >> 6;
    const int it1 = it1raw < 9 ? it1raw : 9;
    const uint32_t kb = smu + 33792;

    const int cc = tid & 7;
    const int rb = tid >> 3;
    uint32_t dstj[4];
#pragma unroll
    for (int j = 0; j < 4; j++) {
        uint32_t off = (j * 16 + rb) * 128 + cc * 16;
        dstj[j] = kb + (off ^ ((off >> 3) & 0x70));
    }
    const __nv_bfloat16* khp = Kh + (size_t)rb * HD + cc * 8;
    const __nv_bfloat16* klp = Kl + (size_t)rb * HD + cc * 8;
    const __nv_bfloat16* vhp = Vh + (size_t)rb * S_LEN + cc * 8;
    const __nv_bfloat16* vlp = Vl + (size_t)rb * S_LEN + cc * 8;

    auto load_kv = [&](int ks0) {
        const __nv_bfloat16* kh = khp + (size_t)ks0 * HD;
        const __nv_bfloat16* kl = klp + (size_t)ks0 * HD;
        const __nv_bfloat16* vh = vhp + ks0;
        const __nv_bfloat16* vl = vlp + ks0;
#pragma unroll
        for (int j = 0; j < 4; j++) CP_ASYNC16(dstj[j],          kh + j * (16 * HD));
#pragma unroll
        for (int j = 0; j < 4; j++) CP_ASYNC16(dstj[j] + 8192,   kl + j * (16 * HD));
#pragma unroll
        for (int j = 0; j < 4; j++) CP_ASYNC16(dstj[j] + 16384,  vh + j * (16 * S_LEN));
#pragma unroll
        for (int j = 0; j < 4; j++) CP_ASYNC16(dstj[j] + 24576,  vl + j * (16 * S_LEN));
        CP_ASYNC_COMMIT();
    };
    load_kv(q0 - 256 + it0 * 64);

    float o[64];
#pragma unroll
    for (int j = 0; j < 64; j++) o[j] = 0.0f;
    float m = -1e30f, l = 0.0f;
    int ph = 0;

#pragma unroll 1
    for (int t = it0; t <= it1; t++) {
        const int ks0 = q0 - 256 + t * 64;

        CP_ASYNC_WAIT0();
        FENCE_PROXY_ASYNC();
        __syncthreads();

        if (wid == 0) {
            if (elect_one_pred()) {
                uint64_t dQh = MAKE_SMEM_DESC(smu + 1024);
                uint64_t dQl = MAKE_SMEM_DESC(smu + 1024 + 16384);
                uint64_t dKh = MAKE_SMEM_DESC(kb);
                uint64_t dKl = MAKE_SMEM_DESC(kb + 8192);
#pragma unroll
                for (int ks = 0; ks < 4; ks++) {
                    mma_bf16_ss(tmem, dQh + ks * 2, dKh + ks * 2, ATT_IDESC, ks > 0);
                    mma_bf16_ss(tmem, dQh + ks * 2, dKl + ks * 2, ATT_IDESC, true);
                    mma_bf16_ss(tmem, dQl + ks * 2, dKh + ks * 2, ATT_IDESC, true);
                }
                TCGEN05_COMMIT(smu + 8);
            }
        }
        MBARRIER_WAIT_PARITY(smu + 8, ph); ph ^= 1;
        TCGEN05_FENCE_AFTER();

        float s[64];
        TCGEN05_LD_X32(reinterpret_cast<uint32_t*>(s), tmem);
        TCGEN05_LD_X32(reinterpret_cast<uint32_t*>(s) + 32, tmem + 32);
        TCGEN05_WAIT_LD();

        const bool interior = (ks0 >= gq - HALF_W) && (ks0 + 63 <= gq + HALF_W);
        float mnew, corr, rs = 0.0f;
        if (interior) {
            float tmax = s[0];
#pragma unroll
            for (int j = 1; j < 64; j++) tmax = fmaxf(tmax, s[j]);
            mnew = fmaxf(m, tmax);
            corr = __expf(m - mnew);
#pragma unroll
            for (int j = 0; j < 64; j++) {
                float p = __expf(s[j] - mnew);
                s[j] = p;
                rs += p;
            }
        } else {
            float tmax = -1e30f;
#pragma unroll
            for (int j = 0; j < 64; j++) {
                int dk = ks0 + j - gq;
                bool ok = (dk >= -HALF_W) && (dk <= HALF_W);
                s[j] = ok ? s[j] : -1e30f;
                tmax = fmaxf(tmax, s[j]);
            }
            mnew = fmaxf(m, tmax);
            corr = __expf(m - mnew);
#pragma unroll
            for (int j = 0; j < 64; j++) {
                float p = (s[j] > -1e29f) ? __expf(s[j] - mnew) : 0.0f;
                s[j] = p;
                rs += p;
            }
        }
        l = l * corr + rs;
        m = mnew;

        {
            const int row = wid * 32 + lid;
#pragma unroll
            for (int c8 = 0; c8 < 8; c8++) {
                float v0 = s[c8 * 8 + 0], v1 = s[c8 * 8 + 1], v2 = s[c8 * 8 + 2], v3 = s[c8 * 8 + 3];
                float v4 = s[c8 * 8 + 4], v5 = s[c8 * 8 + 5], v6 = s[c8 * 8 + 6], v7 = s[c8 * 8 + 7];
                uint32_t off = row * 128 + c8 * 16;
                uint32_t sw = off ^ ((off >> 3) & 0x70);
                STS128(smu + 66560 + sw, pk2(v0, v1), pk2(v2, v3), pk2(v4, v5), pk2(v6, v7));
                float h0 = bfi(v0), h1 = bfi(v1), h2 = bfi(v2), h3 = bfi(v3);
                float h4 = bfi(v4), h5 = bfi(v5), h6 = bfi(v6), h7 = bfi(v7);
                STS128(smu + 82944 + sw, pk2(v0 - h0, v1 - h1), pk2(v2 - h2, v3 - h3),
                       pk2(v4 - h4, v5 - h5), pk2(v6 - h6, v7 - h7));
            }
        }
        FENCE_PROXY_ASYNC();
        __syncthreads();

        if (wid == 0) {
            if (elect_one_pred()) {
                uint64_t dPh = MAKE_SMEM_DESC(smu + 66560);
                uint64_t dPl = MAKE_SMEM_DESC(smu + 82944);
                uint64_t dVh = MAKE_SMEM_DESC(kb + 16384);
                uint64_t dVl = MAKE_SMEM_DESC(kb + 24576);
#pragma unroll
                for (int ks = 0; ks < 4; ks++) {
                    mma_bf16_ss(tmem + 64, dPh + ks * 2, dVh + ks * 2, ATT_IDESC, ks > 0);
                    mma_bf16_ss(tmem + 64, dPh + ks * 2, dVl + ks * 2, ATT_IDESC, true);
                    mma_bf16_ss(tmem + 64, dPl + ks * 2, dVh + ks * 2, ATT_IDESC, true);
                }
                TCGEN05_COMMIT(smu + 8);
            }
        }
        MBARRIER_WAIT_PARITY(smu + 8, ph); ph ^= 1;
        TCGEN05_FENCE_AFTER();

        if (t < it1) load_kv(ks0 + 64);

        {
            float pv[32];
            TCGEN05_LD_X32(reinterpret_cast<uint32_t*>(pv), tmem + 64);
            TCGEN05_WAIT_LD();
#pragma unroll
            for (int j = 0; j < 32; j++) o[j] = o[j] * corr + pv[j];
            TCGEN05_LD_X32(reinterpret_cast<uint32_t*>(pv), tmem + 96);
            TCGEN05_WAIT_LD();
#pragma unroll
            for (int j = 0; j < 32; j++) o[32 + j] = o[32 + j] * corr + pv[j];
        }
    }

    {
        float inv = 1.0f / l;
        size_t ob = ((size_t)b * S_LEN + gq) * ED + h * HD;
#pragma unroll
        for (int c8 = 0; c8 < 8; c8++) {
            float v0 = o[c8 * 8 + 0] * inv, v1 = o[c8 * 8 + 1] * inv;
            float v2 = o[c8 * 8 + 2] * inv, v3 = o[c8 * 8 + 3] * inv;
            float v4 = o[c8 * 8 + 4] * inv, v5 = o[c8 * 8 + 5] * inv;
            float v6 = o[c8 * 8 + 6] * inv, v7 = o[c8 * 8 + 7] * inv;
            uint4 H = make_uint4(pk2(v0, v1), pk2(v2, v3), pk2(v4, v5), pk2(v6, v7));
            float h0 = bfi(v0), h1 = bfi(v1), h2 = bfi(v2), h3 = bfi(v3);
            float h4 = bfi(v4), h5 = bfi(v5), h6 = bfi(v6), h7 = bfi(v7);
            uint4 L = make_uint4(pk2(v0 - h0, v1 - h1), pk2(v2 - h2, v3 - h3),
                                 pk2(v4 - h4, v5 - h5), pk2(v6 - h6, v7 - h7));
            *reinterpret_cast<uint4*>(Ohi + ob + c8 * 8) = H;
            *reinterpret_cast<uint4*>(Olo + ob + c8 * 8) = L;
        }
    }
    __syncthreads();
    if (wid == 0) TCGEN05_DEALLOC(tmem, 128);
#else
    // ---------------- naive fallback (never selected on GB300) ----------------
    (void)smc;
    const int row = gq;
    float o[64];
#pragma unroll
    for (int j = 0; j < 64; j++) o[j] = 0.0f;
    float mm = -1e30f, ll = 0.0f;
    int k0 = row - HALF_W < 0 ? 0 : row - HALF_W;
    int k1 = row + HALF_W > S_LEN - 1 ? S_LEN - 1 : row + HALF_W;
    for (int gk = k0; gk <= k1; gk++) {
        float sc = 0.0f;
        for (int d = 0; d < 64; d++)
            sc += (__bfloat162float(Qh[(size_t)row * HD + d]) + __bfloat162float(Ql[(size_t)row * HD + d])) *
                  (__bfloat162float(Kh[(size_t)gk * HD + d]) + __bfloat162float(Kl[(size_t)gk * HD + d]));
        float mn = fmaxf(mm, sc);
        float corr = __expf(mm - mn);
        float p = __expf(sc - mn);
        ll = ll * corr + p;
        for (int d = 0; d < 64; d++)
            o[d] = o[d] * corr + p * (__bfloat162float(Vh[(size_t)d * S_LEN + gk]) +
                                      __bfloat162float(Vl[(size_t)d * S_LEN + gk]));
        mm = mn;
    }
    float inv = 1.0f / ll;
    size_t ob = ((size_t)b * S_LEN + row) * ED + h * HD;
    for (int d = 0; d < 64; d++) {
        float v = o[d] * inv;
        float hf = bfi(v);
        Ohi[ob + d] = __float2bfloat16(v);
        Olo[ob + d] = __float2bfloat16(v - hf);
    }
#endif
}

// ---------------------------------------------------------------------------
extern "C" void kernel_launch(void* const* d_in, const int* in_sizes, int n_in,
                              void* d_out, int out_size)
{
    (void)in_sizes; (void)n_in; (void)out_size;
    const float* x  = (const float*)d_in[0];
    const float* Wq = (const float*)d_in[1];
    const float* bq = (const float*)d_in[2];
    const float* Wk = (const float*)d_in[3];
    const float* bk = (const float*)d_in[4];
    const float* Wv = (const float*)d_in[5];
    const float* bv = (const float*)d_in[6];
    const float* Wo = (const float*)d_in[7];
    const float* bo = (const float*)d_in[8];

    __nv_bfloat16 *xhi, *xlo, *whi, *wlo, *qkvh, *qkvl, *ahi, *alo;
    cudaGetSymbolAddress((void**)&xhi, g_xhi);
    cudaGetSymbolAddress((void**)&xlo, g_xlo);
    cudaGetSymbolAddress((void**)&whi, g_whi);
    cudaGetSymbolAddress((void**)&wlo, g_wlo);
    cudaGetSymbolAddress((void**)&qkvh, g_qkvh);
    cudaGetSymbolAddress((void**)&qkvl, g_qkvl);
    cudaGetSymbolAddress((void**)&ahi, g_ahi);
    cudaGetSymbolAddress((void**)&alo, g_alo);

    cudaFuncSetAttribute(gemm_bf16x3, cudaFuncAttributeMaxDynamicSharedMemorySize, GEMM_SMEM);
    cudaFuncSetAttribute(attn_tc_kernel, cudaFuncAttributeMaxDynamicSharedMemorySize, ATT_SMEM);

    prep_kernel<<<8192, 256>>>(x, Wq, Wk, Wv, Wo, xhi, xlo, whi, wlo);

    gemm_bf16x3<<<dim3(24, 32), 256, GEMM_SMEM>>>(xhi, xlo, whi, wlo,
                                                  bq, bk, bv, nullptr, qkvh, qkvl, 1);

    attn_tc_kernel<<<dim3(S_LEN / 128, NH, BATCH), 128, ATT_SMEM>>>(qkvh, qkvl, ahi, alo);

    gemm_bf16x3<<<dim3(8, 32), 256, GEMM_SMEM>>>(ahi, alo,
                                                 whi + (size_t)3 * ED * ED, wlo + (size_t)3 * ED * ED,
                                                 bo, bo, bo, (float*)d_out, nullptr, nullptr, 0);
}

// round 12
// speedup vs baseline: 1.1026x; 1.1026x over previous
#include <cuda_runtime.h>
#include <cuda_bf16.h>
#include <cstdint>

#define BATCH 2
#define S_LEN 2048
#define ED    1024
#define NH    16
#define HD    64
#define HALF_W 256
#define MROWS (BATCH * S_LEN)   // 4096

#if defined(__CUDA_ARCH_FEAT_SM103_ALL) || defined(__CUDA_ARCH_FEAT_SM100_ALL)
#define HAS_TCGEN05 1
#else
#define HAS_TCGEN05 0
#endif

// ---------------------------------------------------------------------------
// Scratch (device globals)
// ---------------------------------------------------------------------------
__device__ __nv_bfloat16 g_xhi[MROWS * ED];
__device__ __nv_bfloat16 g_xlo[MROWS * ED];
__device__ __nv_bfloat16 g_whi[4 * ED * ED];   // transposed weights [z][n][k]
__device__ __nv_bfloat16 g_wlo[4 * ED * ED];
__device__ __nv_bfloat16 g_qkvh[3 * MROWS * ED];  // Q,K: [b,h,s,d]; V: [b,h,d,s]
__device__ __nv_bfloat16 g_qkvl[3 * MROWS * ED];
__device__ __nv_bfloat16 g_ahi[MROWS * ED];
__device__ __nv_bfloat16 g_alo[MROWS * ED];

// ---------------------------------------------------------------------------
// PTX helpers
// ---------------------------------------------------------------------------
__device__ __forceinline__ uint32_t smem_to_u32(const void* p) {
    uint32_t a;
    asm("{ .reg .u64 t; cvta.to.shared.u64 t, %1; cvt.u32.u64 %0, t; }" : "=r"(a) : "l"(p));
    return a;
}
#if HAS_TCGEN05
__device__ __forceinline__ uint32_t elect_one_pred() {
    uint32_t pred;
    asm volatile("{\n\t.reg .pred p;\n\telect.sync _|p, 0xFFFFFFFF;\n\tselp.b32 %0, 1, 0, p;\n\t}" : "=r"(pred));
    return pred;
}
#endif
#define MBARRIER_INIT(addr, cnt) \
    asm volatile("mbarrier.init.shared.b64 [%0], %1;" :: "r"((uint32_t)(addr)), "r"((uint32_t)(cnt)) : "memory")
#define MBARRIER_WAIT_PARITY(addr, par) do { \
    uint32_t _m = (uint32_t)(addr); uint32_t _p = (uint32_t)(par); uint32_t _d; \
    asm volatile("{\n\t.reg .pred p;\n\tmbarrier.try_wait.parity.acquire.cta.shared::cta.b64 p, [%1], %2;\n\tselp.b32 %0, 1, 0, p;\n\t}" \
        : "=r"(_d) : "r"(_m), "r"(_p) : "memory"); \
    if (!_d) { \
        asm volatile("{\n\t.reg .pred P1;\n\tWL_%=:\n\tmbarrier.try_wait.parity.acquire.cta.shared::cta.b64 P1, [%0], %1, 0x989680;\n\t@P1 bra.uni WD_%=;\n\tbra.uni WL_%=;\n\tWD_%=:\n\t}" \
            :: "r"(_m), "r"(_p) : "memory"); \
    } } while (0)
#define TCGEN05_ALLOC(sres, nc) \
    asm volatile("tcgen05.alloc.cta_group::1.sync.aligned.shared::cta.b32 [%0], %1;" :: "r"((uint32_t)(sres)), "r"((uint32_t)(nc)) : "memory")
#define TCGEN05_DEALLOC(tm, nc) \
    asm volatile("tcgen05.dealloc.cta_group::1.sync.aligned.b32 %0, %1;" :: "r"(tm), "r"((uint32_t)(nc)))
#define TCGEN05_RELINQ() \
    asm volatile("tcgen05.relinquish_alloc_permit.cta_group::1.sync.aligned;")
#define TCGEN05_COMMIT(mb) \
    asm volatile("tcgen05.commit.cta_group::1.mbarrier::arrive::one.shared::cluster.b64 [%0];" :: "r"((uint32_t)(mb)) : "memory")
#define TCGEN05_FENCE_AFTER() asm volatile("tcgen05.fence::after_thread_sync;" ::: "memory")
#define TCGEN05_WAIT_LD() asm volatile("tcgen05.wait::ld.sync.aligned;" ::: "memory")
#define FENCE_PROXY_ASYNC() asm volatile("fence.proxy.async.shared::cta;" ::: "memory")
#define CP_ASYNC16(saddr, gptr) \
    asm volatile("cp.async.cg.shared.global [%0], [%1], 16;" :: "r"((uint32_t)(saddr)), "l"(gptr) : "memory")
#define CP_ASYNC_COMMIT() asm volatile("cp.async.commit_group;" ::: "memory")
#define CP_ASYNC_WAIT0()  asm volatile("cp.async.wait_group 0;" ::: "memory")
#define STS128(addr, a, b, c, d) \
    asm volatile("st.shared.v4.b32 [%0], {%1, %2, %3, %4};" :: "r"((uint32_t)(addr)), "r"(a), "r"(b), "r"(c), "r"(d) : "memory")

#define TCGEN05_LD_X32(r, ta) \
    asm volatile("tcgen05.ld.sync.aligned.32x32b.x32.b32 " \
        "{%0, %1, %2, %3, %4, %5, %6, %7, %8, %9, %10, %11, %12, %13, %14, %15, " \
        " %16, %17, %18, %19, %20, %21, %22, %23, %24, %25, %26, %27, %28, %29, %30, %31}, [%32];" \
        : "=r"((r)[0]), "=r"((r)[1]), "=r"((r)[2]), "=r"((r)[3]), "=r"((r)[4]), "=r"((r)[5]), "=r"((r)[6]), "=r"((r)[7]), \
          "=r"((r)[8]), "=r"((r)[9]), "=r"((r)[10]), "=r"((r)[11]), "=r"((r)[12]), "=r"((r)[13]), "=r"((r)[14]), "=r"((r)[15]), \
          "=r"((r)[16]), "=r"((r)[17]), "=r"((r)[18]), "=r"((r)[19]), "=r"((r)[20]), "=r"((r)[21]), "=r"((r)[22]), "=r"((r)[23]), \
          "=r"((r)[24]), "=r"((r)[25]), "=r"((r)[26]), "=r"((r)[27]), "=r"((r)[28]), "=r"((r)[29]), "=r"((r)[30]), "=r"((r)[31]) \
        : "r"(ta))

// SMEM descriptor: K-major SW128, LBO=1, SBO=64, version=1
static constexpr uint64_t SMEM_DESC_BASE_SW128 =
    (uint64_t(2) << 61) | (uint64_t(1) << 46) | (uint64_t(64) << 32) | (uint64_t(1) << 16);
#define MAKE_SMEM_DESC(a) (SMEM_DESC_BASE_SW128 | ((uint64_t)((a) >> 4) & 0x3FFF))

// idesc: dtype F32 (bit4), atype BF16 (bit7), btype BF16 (bit10)
static constexpr uint32_t GEMM_IDESC = (8u << 24) | (16u << 17) | (1u << 10) | (1u << 7) | (1u << 4); // M128 N128
static constexpr uint32_t ATT_IDESC  = (8u << 24) | (8u << 17)  | (1u << 10) | (1u << 7) | (1u << 4); // M128 N64

#if HAS_TCGEN05
__device__ __forceinline__ void mma_bf16_ss(uint32_t d_tmem, uint64_t a_desc, uint64_t b_desc,
                                            uint32_t idesc, bool acc) {
    uint32_t en = acc ? 1u : 0u;
    asm volatile(
        "{\n\t.reg .pred p;\n\tsetp.ne.u32 p, %5, 0;\n\t"
        "tcgen05.mma.cta_group::1.kind::f16 [%0], %1, %2, %3, {%4, %4, %4, %4}, p;\n\t}"
        :: "r"(d_tmem), "l"(a_desc), "l"(b_desc), "r"(idesc), "r"(0u), "r"(en) : "memory");
}
#endif

__device__ __forceinline__ uint32_t pk2(float a, float b) {
    __nv_bfloat162 t = __floats2bfloat162_rn(a, b);
    return *reinterpret_cast<uint32_t*>(&t);
}
__device__ __forceinline__ float bfi(float v) {
    return __bfloat162float(__float2bfloat16(v));
}

// ---------------------------------------------------------------------------
// Merged prep kernel
// ---------------------------------------------------------------------------
__global__ __launch_bounds__(256) void prep_kernel(
    const float* __restrict__ x,
    const float* __restrict__ Wq, const float* __restrict__ Wk,
    const float* __restrict__ Wv, const float* __restrict__ Wo,
    __nv_bfloat16* __restrict__ xhi, __nv_bfloat16* __restrict__ xlo,
    __nv_bfloat16* __restrict__ whi, __nv_bfloat16* __restrict__ wlo)
{
    const int tid = threadIdx.x;
    if (blockIdx.x < 4096) {
        int i = blockIdx.x * 256 + tid;
        float4 v = reinterpret_cast<const float4*>(x)[i];
        float h0 = bfi(v.x), h1 = bfi(v.y), h2 = bfi(v.z), h3 = bfi(v.w);
        reinterpret_cast<uint2*>(xhi)[i] = make_uint2(pk2(v.x, v.y), pk2(v.z, v.w));
        reinterpret_cast<uint2*>(xlo)[i] = make_uint2(pk2(v.x - h0, v.y - h1), pk2(v.z - h2, v.w - h3));
    } else {
        __shared__ float ts[32][33];
        int bid = blockIdx.x - 4096;
        int z = bid >> 10;
        int rem = bid & 1023;
        int n0 = (rem & 31) * 32, k0 = (rem >> 5) * 32;
        const float* W = (z == 0) ? Wq : (z == 1) ? Wk : (z == 2) ? Wv : Wo;
        int tx = tid & 31, ty = tid >> 5;
        for (int r = ty; r < 32; r += 8)
            ts[r][tx] = W[(size_t)(k0 + r) * ED + n0 + tx];
        __syncthreads();
        size_t zoff = (size_t)z * ED * ED;
        for (int r = ty; r < 32; r += 8) {
            float v = ts[tx][r];
            float hf = bfi(v);
            size_t o = zoff + (size_t)(n0 + r) * ED + k0 + tx;
            whi[o] = __float2bfloat16(v);
            wlo[o] = __float2bfloat16(v - hf);
        }
    }
}

// ---------------------------------------------------------------------------
// bf16x3 tcgen05 GEMM — round-10 version (K-tile 64, single buffer, occ 2,
// hoisted cp.async addressing, 8-warp epilogue).
// ---------------------------------------------------------------------------
#define GEMM_SMEM (1024 + 65536)

__global__ __launch_bounds__(256, 2) void gemm_bf16x3(
    const __nv_bfloat16* __restrict__ Ahi, const __nv_bfloat16* __restrict__ Alo,
    const __nv_bfloat16* __restrict__ Wh,  const __nv_bfloat16* __restrict__ Wl,
    const float* __restrict__ b0, const float* __restrict__ b1, const float* __restrict__ b2,
    float* __restrict__ cf, __nv_bfloat16* __restrict__ chi, __nv_bfloat16* __restrict__ clo,
    int mode)
{
    extern __shared__ char smc[];
    const int tid = threadIdx.x;
    const int wid = tid >> 5, lid = tid & 31;
    const int cRow = blockIdx.y;
    const int z    = mode ? (blockIdx.x >> 3) : 0;
    const int ncol = mode ? (blockIdx.x & 7) : blockIdx.x;

    const __nv_bfloat16* gA0 = Ahi + (size_t)cRow * 128 * ED;
    const __nv_bfloat16* gA1 = Alo + (size_t)cRow * 128 * ED;
    const __nv_bfloat16* gB0 = Wh + ((size_t)z * ED + ncol * 128) * ED;
    const __nv_bfloat16* gB1 = Wl + ((size_t)z * ED + ncol * 128) * ED;
    const float* bias = mode ? ((z == 0) ? b0 : (z == 1) ? b1 : b2) : b0;

#if HAS_TCGEN05
    const uint32_t smu = smem_to_u32(smc);
    const uint32_t bufu = smu + 1024;

    if (tid == 0) MBARRIER_INIT(smu + 8, 1);
    if (wid == 0) { TCGEN05_ALLOC(smu, 128); TCGEN05_RELINQ(); }
    __syncthreads();
    uint32_t tmem;
    asm volatile("ld.shared.b32 %0, [%1];" : "=r"(tmem) : "r"(smu));

    // Hoisted addressing: c = tid&7 (16B chunk), rb = tid>>3 (row 0..31);
    // each part covers rows j*32+rb, j=0..3.
    const int cc = tid & 7;
    const int rb = tid >> 3;
    uint32_t dstj[4];
#pragma unroll
    for (int j = 0; j < 4; j++) {
        uint32_t off = (j * 32 + rb) * 128 + cc * 16;
        dstj[j] = bufu + (off ^ ((off >> 3) & 0x70));
    }
    const __nv_bfloat16* a0p = gA0 + (size_t)rb * ED + cc * 8;
    const __nv_bfloat16* a1p = gA1 + (size_t)rb * ED + cc * 8;
    const __nv_bfloat16* b0p = gB0 + (size_t)rb * ED + cc * 8;
    const __nv_bfloat16* b1p = gB1 + (size_t)rb * ED + cc * 8;

    auto load_tile = [&](int k0e) {
#pragma unroll
        for (int j = 0; j < 4; j++) CP_ASYNC16(dstj[j],          a0p + k0e + j * (32 * ED));
#pragma unroll
        for (int j = 0; j < 4; j++) CP_ASYNC16(dstj[j] + 16384,  a1p + k0e + j * (32 * ED));
#pragma unroll
        for (int j = 0; j < 4; j++) CP_ASYNC16(dstj[j] + 32768,  b0p + k0e + j * (32 * ED));
#pragma unroll
        for (int j = 0; j < 4; j++) CP_ASYNC16(dstj[j] + 49152,  b1p + k0e + j * (32 * ED));
        CP_ASYNC_COMMIT();
    };

    load_tile(0);

    int ph = 0;
#pragma unroll 1
    for (int t = 0; t < 16; t++) {
        CP_ASYNC_WAIT0();
        FENCE_PROXY_ASYNC();
        __syncthreads();

        if (wid == 0) {
            if (elect_one_pred()) {
                uint64_t dAh = MAKE_SMEM_DESC(bufu);
                uint64_t dAl = MAKE_SMEM_DESC(bufu + 16384);
                uint64_t dBh = MAKE_SMEM_DESC(bufu + 32768);
                uint64_t dBl = MAKE_SMEM_DESC(bufu + 49152);
#pragma unroll
                for (int ks = 0; ks < 4; ks++) {
                    mma_bf16_ss(tmem, dAh + ks * 2, dBh + ks * 2, GEMM_IDESC, !(t == 0 && ks == 0));
                    mma_bf16_ss(tmem, dAh + ks * 2, dBl + ks * 2, GEMM_IDESC, true);
                    mma_bf16_ss(tmem, dAl + ks * 2, dBh + ks * 2, GEMM_IDESC, true);
                }
                TCGEN05_COMMIT(smu + 8);
            }
        }
        MBARRIER_WAIT_PARITY(smu + 8, ph); ph ^= 1;   // MMA reads of buffer done
        if (t + 1 < 16) load_tile((t + 1) * 64);
    }
    TCGEN05_FENCE_AFTER();

    // 8-warp epilogue: subpartition = wid&3 (lanes), column half = wid>>2.
    {
        const int sub = wid & 3;
        float* wsm = reinterpret_cast<float*>(smc + 1024) + wid * (32 * 33);
#pragma unroll 1
        for (int cc2 = 0; cc2 < 2; cc2++) {
            const int c = (wid >> 2) * 2 + cc2;
            uint32_t regs[32];
            TCGEN05_LD_X32(regs, tmem + c * 32);
            TCGEN05_WAIT_LD();
#pragma unroll
            for (int j = 0; j < 32; j++)
                wsm[lid * 33 + j] = __uint_as_float(regs[j]) + bias[ncol * 128 + c * 32 + j];
            __syncwarp();
            if (mode == 0) {
#pragma unroll
                for (int j = 0; j < 32; j++) {
                    int row = cRow * 128 + sub * 32 + j;
                    int col = ncol * 128 + c * 32 + lid;
                    cf[(size_t)row * ED + col] = wsm[j * 33 + lid];
                }
            } else if (z < 2) {
#pragma unroll
                for (int j = 0; j < 32; j++) {
                    float v = wsm[j * 33 + lid];
                    if (z == 0) v *= 0.125f;
                    int row = cRow * 128 + sub * 32 + j;
                    int col = ncol * 128 + c * 32 + lid;
                    int bb = row >> 11, s = row & 2047;
                    int hh = col >> 6, d = col & 63;
                    float hf = bfi(v);
                    size_t idx = (size_t)z * MROWS * ED + (((size_t)(bb * NH + hh)) * S_LEN + s) * HD + d;
                    chi[idx] = __float2bfloat16(v);
                    clo[idx] = __float2bfloat16(v - hf);
                }
            } else {
#pragma unroll
                for (int j = 0; j < 32; j++) {
                    float v = wsm[lid * 33 + j];
                    int row = cRow * 128 + sub * 32 + lid;
                    int col = ncol * 128 + c * 32 + j;
                    int bb = row >> 11, s = row & 2047;
                    int hh = col >> 6, d = col & 63;
                    float hf = bfi(v);
                    size_t idx = (size_t)2 * MROWS * ED + (((size_t)(bb * NH + hh)) * HD + d) * S_LEN + s;
                    chi[idx] = __float2bfloat16(v);
                    clo[idx] = __float2bfloat16(v - hf);
                }
            }
            __syncwarp();
        }
    }
    __syncthreads();
    if (wid == 0) TCGEN05_DEALLOC(tmem, 128);
#else
    // ---------------- FFMA fallback (never selected on GB300) ----------------
    float* As = reinterpret_cast<float*>(smc);
    float* Bs = As + 16 * 132;
    const int threadRow = tid / 16;
    const int threadCol = tid % 16;

    float acc[8][8];
#pragma unroll
    for (int i = 0; i < 8; i++)
#pragma unroll
        for (int j = 0; j < 8; j++) acc[i][j] = 0.0f;

    for (int k0 = 0; k0 < ED; k0 += 16) {
        for (int i = tid; i < 2048; i += 256) {
            int r = i >> 4, kk = i & 15;
            As[kk * 132 + r] = __bfloat162float(gA0[(size_t)r * ED + k0 + kk]) +
                               __bfloat162float(gA1[(size_t)r * ED + k0 + kk]);
            Bs[kk * 132 + r] = __bfloat162float(gB0[(size_t)r * ED + k0 + kk]) +
                               __bfloat162float(gB1[(size_t)r * ED + k0 + kk]);
        }
        __syncthreads();
#pragma unroll
        for (int kk = 0; kk < 16; kk++) {
            float regM[8], regN[8];
#pragma unroll
            for (int i = 0; i < 8; i++) regM[i] = As[kk * 132 + threadRow * 8 + i];
#pragma unroll
            for (int j = 0; j < 8; j++) regN[j] = Bs[kk * 132 + threadCol * 8 + j];
#pragma unroll
            for (int i = 0; i < 8; i++)
#pragma unroll
                for (int j = 0; j < 8; j++)
                    acc[i][j] = fmaf(regM[i], regN[j], acc[i][j]);
        }
        __syncthreads();
    }

#pragma unroll
    for (int i = 0; i < 8; i++) {
        int row = cRow * 128 + threadRow * 8 + i;
#pragma unroll
        for (int j = 0; j < 8; j++) {
            int col = ncol * 128 + threadCol * 8 + j;
            float v = acc[i][j] + bias[col];
            if (mode == 0) {
                cf[(size_t)row * ED + col] = v;
            } else {
                int bb = row >> 11, s = row & 2047;
                int hh = col >> 6, d = col & 63;
                if (z == 0) v *= 0.125f;
                size_t idx;
                if (z < 2) idx = (size_t)z * MROWS * ED + (((size_t)(bb * NH + hh)) * S_LEN + s) * HD + d;
                else       idx = (size_t)2 * MROWS * ED + (((size_t)(bb * NH + hh)) * HD + d) * S_LEN + s;
                float hf = bfi(v);
                chi[idx] = __float2bfloat16(v);
                clo[idx] = __float2bfloat16(v - hf);
            }
        }
    }
#endif
}

// ---------------------------------------------------------------------------
// Banded flash attention on tcgen05 — occ 2, split K/V prefetch:
// K(t+1) issued right after the S-MMA mbarrier (K's last reader), so the
// K load overlaps softmax + P-pack + PV MMA; V(t+1) after the PV mbarrier.
// smem map: 0 ctrl | 1024 Qhi 16K | 17408 Qlo 16K |
//           33792 Khi 8K | 41984 Klo 8K | 50176 Vhi 8K | 58368 Vlo 8K |
//           66560 Phi 16K | 82944 Plo 16K | total 99328
// ---------------------------------------------------------------------------
#define ATT_SMEM 99328

__global__ __launch_bounds__(128, 2) void attn_tc_kernel(
    const __nv_bfloat16* __restrict__ qkvh, const __nv_bfloat16* __restrict__ qkvl,
    __nv_bfloat16* __restrict__ Ohi, __nv_bfloat16* __restrict__ Olo)
{
    extern __shared__ char smc[];
    const int tid = threadIdx.x;
    const int wid = tid >> 5, lid = tid & 31;
    const int b = blockIdx.z, h = blockIdx.y;
    const int q0 = blockIdx.x * 128;
    const size_t bh = (size_t)(b * NH + h);

    const __nv_bfloat16* Qh = qkvh + bh * S_LEN * HD;
    const __nv_bfloat16* Ql = qkvl + bh * S_LEN * HD;
    const __nv_bfloat16* Kh = qkvh + (size_t)MROWS * ED + bh * S_LEN * HD;
    const __nv_bfloat16* Kl = qkvl + (size_t)MROWS * ED + bh * S_LEN * HD;
    const __nv_bfloat16* Vh = qkvh + (size_t)2 * MROWS * ED + bh * HD * S_LEN;
    const __nv_bfloat16* Vl = qkvl + (size_t)2 * MROWS * ED + bh * HD * S_LEN;

    const int gq = q0 + wid * 32 + lid;

#if HAS_TCGEN05
    const uint32_t smu = smem_to_u32(smc);

    if (tid == 0) MBARRIER_INIT(smu + 8, 1);
    if (wid == 0) { TCGEN05_ALLOC(smu, 128); TCGEN05_RELINQ(); }
    __syncthreads();
    uint32_t tmem;
    asm volatile("ld.shared.b32 %0, [%1];" : "=r"(tmem) : "r"(smu));

    // Load Q hi/lo (128 rows x 64 bf16, SW128)
#pragma unroll
    for (int i = 0; i < 16; i++) {
        int idx = i * 128 + tid;
        int arr = idx >> 10;
        int r = (idx >> 3) & 127, c = idx & 7;
        const __nv_bfloat16* src = arr ? Ql : Qh;
        uint32_t off = r * 128 + c * 16;
        CP_ASYNC16(smu + 1024 + arr * 16384 + (off ^ ((off >> 3) & 0x70)),
                   src + (size_t)(q0 + r) * HD + c * 8);
    }
    CP_ASYNC_COMMIT();

    const int it0 = (q0 < 256) ? ((256 - q0) >> 6) : 0;
    const int it1raw = (2240 - q0) >> 6;
    const int it1 = it1raw < 9 ? it1raw : 9;
    const uint32_t kb = smu + 33792;

    const int cc = tid & 7;
    const int rb = tid >> 3;
    uint32_t dstj[4];
#pragma unroll
    for (int j = 0; j < 4; j++) {
        uint32_t off = (j * 16 + rb) * 128 + cc * 16;
        dstj[j] = kb + (off ^ ((off >> 3) & 0x70));
    }
    const __nv_bfloat16* khp = Kh + (size_t)rb * HD + cc * 8;
    const __nv_bfloat16* klp = Kl + (size_t)rb * HD + cc * 8;
    const __nv_bfloat16* vhp = Vh + (size_t)rb * S_LEN + cc * 8;
    const __nv_bfloat16* vlp = Vl + (size_t)rb * S_LEN + cc * 8;

    auto load_k = [&](int ks0) {
        const __nv_bfloat16* kh = khp + (size_t)ks0 * HD;
        const __nv_bfloat16* kl = klp + (size_t)ks0 * HD;
#pragma unroll
        for (int j = 0; j < 4; j++) CP_ASYNC16(dstj[j],          kh + j * (16 * HD));
#pragma unroll
        for (int j = 0; j < 4; j++) CP_ASYNC16(dstj[j] + 8192,   kl + j * (16 * HD));
        CP_ASYNC_COMMIT();
    };
    auto load_v = [&](int ks0) {
        const __nv_bfloat16* vh = vhp + ks0;
        const __nv_bfloat16* vl = vlp + ks0;
#pragma unroll
        for (int j = 0; j < 4; j++) CP_ASYNC16(dstj[j] + 16384,  vh + j * (16 * S_LEN));
#pragma unroll
        for (int j = 0; j < 4; j++) CP_ASYNC16(dstj[j] + 24576,  vl + j * (16 * S_LEN));
        CP_ASYNC_COMMIT();
    };
    load_k(q0 - 256 + it0 * 64);
    load_v(q0 - 256 + it0 * 64);

    float o[64];
#pragma unroll
    for (int j = 0; j < 64; j++) o[j] = 0.0f;
    float m = -1e30f, l = 0.0f;
    int ph = 0;

#pragma unroll 1
    for (int t = it0; t <= it1; t++) {
        const int ks0 = q0 - 256 + t * 64;

        CP_ASYNC_WAIT0();      // K(t), V(t) (and any earlier groups) complete
        FENCE_PROXY_ASYNC();
        __syncthreads();

        // S = Q . K^T  (bf16x3), D -> TMEM cols 0-63
        if (wid == 0) {
            if (elect_one_pred()) {
                uint64_t dQh = MAKE_SMEM_DESC(smu + 1024);
                uint64_t dQl = MAKE_SMEM_DESC(smu + 1024 + 16384);
                uint64_t dKh = MAKE_SMEM_DESC(kb);
                uint64_t dKl = MAKE_SMEM_DESC(kb + 8192);
#pragma unroll
                for (int ks = 0; ks < 4; ks++) {
                    mma_bf16_ss(tmem, dQh + ks * 2, dKh + ks * 2, ATT_IDESC, ks > 0);
                    mma_bf16_ss(tmem, dQh + ks * 2, dKl + ks * 2, ATT_IDESC, true);
                    mma_bf16_ss(tmem, dQl + ks * 2, dKh + ks * 2, ATT_IDESC, true);
                }
                TCGEN05_COMMIT(smu + 8);
            }
        }
        MBARRIER_WAIT_PARITY(smu + 8, ph); ph ^= 1;
        TCGEN05_FENCE_AFTER();

        // K buffer free (S MMA done) — prefetch K(t+1) now; it overlaps
        // softmax + P pack + PV MMA below.
        if (t < it1) load_k(ks0 + 64);

        float s[64];
        TCGEN05_LD_X32(reinterpret_cast<uint32_t*>(s), tmem);
        TCGEN05_LD_X32(reinterpret_cast<uint32_t*>(s) + 32, tmem + 32);
        TCGEN05_WAIT_LD();

        const bool interior = (ks0 >= gq - HALF_W) && (ks0 + 63 <= gq + HALF_W);
        float mnew, corr, rs = 0.0f;
        if (interior) {
            float tmax = s[0];
#pragma unroll
            for (int j = 1; j < 64; j++) tmax = fmaxf(tmax, s[j]);
            mnew = fmaxf(m, tmax);
            corr = __expf(m - mnew);
#pragma unroll
            for (int j = 0; j < 64; j++) {
                float p = __expf(s[j] - mnew);
                s[j] = p;
                rs += p;
            }
        } else {
            float tmax = -1e30f;
#pragma unroll
            for (int j = 0; j < 64; j++) {
                int dk = ks0 + j - gq;
                bool ok = (dk >= -HALF_W) && (dk <= HALF_W);
                s[j] = ok ? s[j] : -1e30f;
                tmax = fmaxf(tmax, s[j]);
            }
            mnew = fmaxf(m, tmax);
            corr = __expf(m - mnew);
#pragma unroll
            for (int j = 0; j < 64; j++) {
                float p = (s[j] > -1e29f) ? __expf(s[j] - mnew) : 0.0f;
                s[j] = p;
                rs += p;
            }
        }
        l = l * corr + rs;
        m = mnew;

        {
            const int row = wid * 32 + lid;
#pragma unroll
            for (int c8 = 0; c8 < 8; c8++) {
                float v0 = s[c8 * 8 + 0], v1 = s[c8 * 8 + 1], v2 = s[c8 * 8 + 2], v3 = s[c8 * 8 + 3];
                float v4 = s[c8 * 8 + 4], v5 = s[c8 * 8 + 5], v6 = s[c8 * 8 + 6], v7 = s[c8 * 8 + 7];
                uint32_t off = row * 128 + c8 * 16;
                uint32_t sw = off ^ ((off >> 3) & 0x70);
                STS128(smu + 66560 + sw, pk2(v0, v1), pk2(v2, v3), pk2(v4, v5), pk2(v6, v7));
                float h0 = bfi(v0), h1 = bfi(v1), h2 = bfi(v2), h3 = bfi(v3);
                float h4 = bfi(v4), h5 = bfi(v5), h6 = bfi(v6), h7 = bfi(v7);
                STS128(smu + 82944 + sw, pk2(v0 - h0, v1 - h1), pk2(v2 - h2, v3 - h3),
                       pk2(v4 - h4, v5 - h5), pk2(v6 - h6, v7 - h7));
            }
        }
        FENCE_PROXY_ASYNC();
        __syncthreads();

        // PV = P . V^T (bf16x3), fresh accumulate, D -> TMEM cols 64-127
        if (wid == 0) {
            if (elect_one_pred()) {
                uint64_t dPh = MAKE_SMEM_DESC(smu + 66560);
                uint64_t dPl = MAKE_SMEM_DESC(smu + 82944);
                uint64_t dVh = MAKE_SMEM_DESC(kb + 16384);
                uint64_t dVl = MAKE_SMEM_DESC(kb + 24576);
#pragma unroll
                for (int ks = 0; ks < 4; ks++) {
                    mma_bf16_ss(tmem + 64, dPh + ks * 2, dVh + ks * 2, ATT_IDESC, ks > 0);
                    mma_bf16_ss(tmem + 64, dPh + ks * 2, dVl + ks * 2, ATT_IDESC, true);
                    mma_bf16_ss(tmem + 64, dPl + ks * 2, dVh + ks * 2, ATT_IDESC, true);
                }
                TCGEN05_COMMIT(smu + 8);
            }
        }
        MBARRIER_WAIT_PARITY(smu + 8, ph); ph ^= 1;
        TCGEN05_FENCE_AFTER();

        // V buffer free — prefetch V(t+1); overlaps the PV LDTM + fold.
        if (t < it1) load_v(ks0 + 64);

        {
            float pv[32];
            TCGEN05_LD_X32(reinterpret_cast<uint32_t*>(pv), tmem + 64);
            TCGEN05_WAIT_LD();
#pragma unroll
            for (int j = 0; j < 32; j++) o[j] = o[j] * corr + pv[j];
            TCGEN05_LD_X32(reinterpret_cast<uint32_t*>(pv), tmem + 96);
            TCGEN05_WAIT_LD();
#pragma unroll
            for (int j = 0; j < 32; j++) o[32 + j] = o[32 + j] * corr + pv[j];
        }
    }

    {
        float inv = 1.0f / l;
        size_t ob = ((size_t)b * S_LEN + gq) * ED + h * HD;
#pragma unroll
        for (int c8 = 0; c8 < 8; c8++) {
            float v0 = o[c8 * 8 + 0] * inv, v1 = o[c8 * 8 + 1] * inv;
            float v2 = o[c8 * 8 + 2] * inv, v3 = o[c8 * 8 + 3] * inv;
            float v4 = o[c8 * 8 + 4] * inv, v5 = o[c8 * 8 + 5] * inv;
            float v6 = o[c8 * 8 + 6] * inv, v7 = o[c8 * 8 + 7] * inv;
            uint4 H = make_uint4(pk2(v0, v1), pk2(v2, v3), pk2(v4, v5), pk2(v6, v7));
            float h0 = bfi(v0), h1 = bfi(v1), h2 = bfi(v2), h3 = bfi(v3);
            float h4 = bfi(v4), h5 = bfi(v5), h6 = bfi(v6), h7 = bfi(v7);
            uint4 L = make_uint4(pk2(v0 - h0, v1 - h1), pk2(v2 - h2, v3 - h3),
                                 pk2(v4 - h4, v5 - h5), pk2(v6 - h6, v7 - h7));
            *reinterpret_cast<uint4*>(Ohi + ob + c8 * 8) = H;
            *reinterpret_cast<uint4*>(Olo + ob + c8 * 8) = L;
        }
    }
    __syncthreads();
    if (wid == 0) TCGEN05_DEALLOC(tmem, 128);
#else
    // ---------------- naive fallback (never selected on GB300) ----------------
    (void)smc;
    const int row = gq;
    float o[64];
#pragma unroll
    for (int j = 0; j < 64; j++) o[j] = 0.0f;
    float mm = -1e30f, ll = 0.0f;
    int k0 = row - HALF_W < 0 ? 0 : row - HALF_W;
    int k1 = row + HALF_W > S_LEN - 1 ? S_LEN - 1 : row + HALF_W;
    for (int gk = k0; gk <= k1; gk++) {
        float sc = 0.0f;
        for (int d = 0; d < 64; d++)
            sc += (__bfloat162float(Qh[(size_t)row * HD + d]) + __bfloat162float(Ql[(size_t)row * HD + d])) *
                  (__bfloat162float(Kh[(size_t)gk * HD + d]) + __bfloat162float(Kl[(size_t)gk * HD + d]));
        float mn = fmaxf(mm, sc);
        float corr = __expf(mm - mn);
        float p = __expf(sc - mn);
        ll = ll * corr + p;
        for (int d = 0; d < 64; d++)
            o[d] = o[d] * corr + p * (__bfloat162float(Vh[(size_t)d * S_LEN + gk]) +
                                      __bfloat162float(Vl[(size_t)d * S_LEN + gk]));
        mm = mn;
    }
    float inv = 1.0f / ll;
    size_t ob = ((size_t)b * S_LEN + row) * ED + h * HD;
    for (int d = 0; d < 64; d++) {
        float v = o[d] * inv;
        float hf = bfi(v);
        Ohi[ob + d] = __float2bfloat16(v);
        Olo[ob + d] = __float2bfloat16(v - hf);
    }
#endif
}

// ---------------------------------------------------------------------------
extern "C" void kernel_launch(void* const* d_in, const int* in_sizes, int n_in,
                              void* d_out, int out_size)
{
    (void)in_sizes; (void)n_in; (void)out_size;
    const float* x  = (const float*)d_in[0];
    const float* Wq = (const float*)d_in[1];
    const float* bq = (const float*)d_in[2];
    const float* Wk = (const float*)d_in[3];
    const float* bk = (const float*)d_in[4];
    const float* Wv = (const float*)d_in[5];
    const float* bv = (const float*)d_in[6];
    const float* Wo = (const float*)d_in[7];
    const float* bo = (const float*)d_in[8];

    __nv_bfloat16 *xhi, *xlo, *whi, *wlo, *qkvh, *qkvl, *ahi, *alo;
    cudaGetSymbolAddress((void**)&xhi, g_xhi);
    cudaGetSymbolAddress((void**)&xlo, g_xlo);
    cudaGetSymbolAddress((void**)&whi, g_whi);
    cudaGetSymbolAddress((void**)&wlo, g_wlo);
    cudaGetSymbolAddress((void**)&qkvh, g_qkvh);
    cudaGetSymbolAddress((void**)&qkvl, g_qkvl);
    cudaGetSymbolAddress((void**)&ahi, g_ahi);
    cudaGetSymbolAddress((void**)&alo, g_alo);

    cudaFuncSetAttribute(gemm_bf16x3, cudaFuncAttributeMaxDynamicSharedMemorySize, GEMM_SMEM);
    cudaFuncSetAttribute(attn_tc_kernel, cudaFuncAttributeMaxDynamicSharedMemorySize, ATT_SMEM);

    prep_kernel<<<8192, 256>>>(x, Wq, Wk, Wv, Wo, xhi, xlo, whi, wlo);

    gemm_bf16x3<<<dim3(24, 32), 256, GEMM_SMEM>>>(xhi, xlo, whi, wlo,
                                                  bq, bk, bv, nullptr, qkvh, qkvl, 1);

    attn_tc_kernel<<<dim3(S_LEN / 128, NH, BATCH), 128, ATT_SMEM>>>(qkvh, qkvl, ahi, alo);

    gemm_bf16x3<<<dim3(8, 32), 256, GEMM_SMEM>>>(ahi, alo,
                                                 whi + (size_t)3 * ED * ED, wlo + (size_t)3 * ED * ED,
                                                 bo, bo, bo, (float*)d_out, nullptr, nullptr, 0);
}

// round 13
// speedup vs baseline: 1.1903x; 1.0796x over previous
#include <cuda_runtime.h>
#include <cuda_bf16.h>
#include <cstdint>

#define BATCH 2
#define S_LEN 2048
#define ED    1024
#define NH    16
#define HD    64
#define HALF_W 256
#define MROWS (BATCH * S_LEN)   // 4096

#if defined(__CUDA_ARCH_FEAT_SM103_ALL) || defined(__CUDA_ARCH_FEAT_SM100_ALL)
#define HAS_TCGEN05 1
#else
#define HAS_TCGEN05 0
#endif

// ---------------------------------------------------------------------------
// Scratch (device globals)
// ---------------------------------------------------------------------------
__device__ __nv_bfloat16 g_xhi[MROWS * ED];
__device__ __nv_bfloat16 g_xlo[MROWS * ED];
__device__ __nv_bfloat16 g_whi[4 * ED * ED];   // transposed weights [z][n][k]
__device__ __nv_bfloat16 g_wlo[4 * ED * ED];
__device__ __nv_bfloat16 g_qkvh[3 * MROWS * ED];  // Q,K: [b,h,s,d]; V: [b,h,d,s]
__device__ __nv_bfloat16 g_qkvl[3 * MROWS * ED];
__device__ __nv_bfloat16 g_ahi[MROWS * ED];
__device__ __nv_bfloat16 g_alo[MROWS * ED];

// ---------------------------------------------------------------------------
// PTX helpers
// ---------------------------------------------------------------------------
__device__ __forceinline__ uint32_t smem_to_u32(const void* p) {
    uint32_t a;
    asm("{ .reg .u64 t; cvta.to.shared.u64 t, %1; cvt.u32.u64 %0, t; }" : "=r"(a) : "l"(p));
    return a;
}
#if HAS_TCGEN05
__device__ __forceinline__ uint32_t elect_one_pred() {
    uint32_t pred;
    asm volatile("{\n\t.reg .pred p;\n\telect.sync _|p, 0xFFFFFFFF;\n\tselp.b32 %0, 1, 0, p;\n\t}" : "=r"(pred));
    return pred;
}
#endif
#define MBARRIER_INIT(addr, cnt) \
    asm volatile("mbarrier.init.shared.b64 [%0], %1;" :: "r"((uint32_t)(addr)), "r"((uint32_t)(cnt)) : "memory")
#define MBARRIER_WAIT_PARITY(addr, par) do { \
    uint32_t _m = (uint32_t)(addr); uint32_t _p = (uint32_t)(par); uint32_t _d; \
    asm volatile("{\n\t.reg .pred p;\n\tmbarrier.try_wait.parity.acquire.cta.shared::cta.b64 p, [%1], %2;\n\tselp.b32 %0, 1, 0, p;\n\t}" \
        : "=r"(_d) : "r"(_m), "r"(_p) : "memory"); \
    if (!_d) { \
        asm volatile("{\n\t.reg .pred P1;\n\tWL_%=:\n\tmbarrier.try_wait.parity.acquire.cta.shared::cta.b64 P1, [%0], %1, 0x989680;\n\t@P1 bra.uni WD_%=;\n\tbra.uni WL_%=;\n\tWD_%=:\n\t}" \
            :: "r"(_m), "r"(_p) : "memory"); \
    } } while (0)
#define TCGEN05_ALLOC(sres, nc) \
    asm volatile("tcgen05.alloc.cta_group::1.sync.aligned.shared::cta.b32 [%0], %1;" :: "r"((uint32_t)(sres)), "r"((uint32_t)(nc)) : "memory")
#define TCGEN05_DEALLOC(tm, nc) \
    asm volatile("tcgen05.dealloc.cta_group::1.sync.aligned.b32 %0, %1;" :: "r"(tm), "r"((uint32_t)(nc)))
#define TCGEN05_RELINQ() \
    asm volatile("tcgen05.relinquish_alloc_permit.cta_group::1.sync.aligned;")
#define TCGEN05_COMMIT(mb) \
    asm volatile("tcgen05.commit.cta_group::1.mbarrier::arrive::one.shared::cluster.b64 [%0];" :: "r"((uint32_t)(mb)) : "memory")
#define TCGEN05_FENCE_AFTER() asm volatile("tcgen05.fence::after_thread_sync;" ::: "memory")
#define TCGEN05_WAIT_LD() asm volatile("tcgen05.wait::ld.sync.aligned;" ::: "memory")
#define FENCE_PROXY_ASYNC() asm volatile("fence.proxy.async.shared::cta;" ::: "memory")
#define CP_ASYNC16(saddr, gptr) \
    asm volatile("cp.async.cg.shared.global [%0], [%1], 16;" :: "r"((uint32_t)(saddr)), "l"(gptr) : "memory")
#define CP_ASYNC_COMMIT() asm volatile("cp.async.commit_group;" ::: "memory")
#define CP_ASYNC_WAIT0()  asm volatile("cp.async.wait_group 0;" ::: "memory")
#define STS128(addr, a, b, c, d) \
    asm volatile("st.shared.v4.b32 [%0], {%1, %2, %3, %4};" :: "r"((uint32_t)(addr)), "r"(a), "r"(b), "r"(c), "r"(d) : "memory")

#define TCGEN05_LD_X32(r, ta) \
    asm volatile("tcgen05.ld.sync.aligned.32x32b.x32.b32 " \
        "{%0, %1, %2, %3, %4, %5, %6, %7, %8, %9, %10, %11, %12, %13, %14, %15, " \
        " %16, %17, %18, %19, %20, %21, %22, %23, %24, %25, %26, %27, %28, %29, %30, %31}, [%32];" \
        : "=r"((r)[0]), "=r"((r)[1]), "=r"((r)[2]), "=r"((r)[3]), "=r"((r)[4]), "=r"((r)[5]), "=r"((r)[6]), "=r"((r)[7]), \
          "=r"((r)[8]), "=r"((r)[9]), "=r"((r)[10]), "=r"((r)[11]), "=r"((r)[12]), "=r"((r)[13]), "=r"((r)[14]), "=r"((r)[15]), \
          "=r"((r)[16]), "=r"((r)[17]), "=r"((r)[18]), "=r"((r)[19]), "=r"((r)[20]), "=r"((r)[21]), "=r"((r)[22]), "=r"((r)[23]), \
          "=r"((r)[24]), "=r"((r)[25]), "=r"((r)[26]), "=r"((r)[27]), "=r"((r)[28]), "=r"((r)[29]), "=r"((r)[30]), "=r"((r)[31]) \
        : "r"(ta))

// SMEM descriptor: K-major SW128, LBO=1, SBO=64, version=1
static constexpr uint64_t SMEM_DESC_BASE_SW128 =
    (uint64_t(2) << 61) | (uint64_t(1) << 46) | (uint64_t(64) << 32) | (uint64_t(1) << 16);
#define MAKE_SMEM_DESC(a) (SMEM_DESC_BASE_SW128 | ((uint64_t)((a) >> 4) & 0x3FFF))

// idesc: dtype F32 (bit4), atype BF16 (bit7), btype BF16 (bit10)
static constexpr uint32_t GEMM_IDESC = (8u << 24) | (16u << 17) | (1u << 10) | (1u << 7) | (1u << 4); // M128 N128
static constexpr uint32_t ATT_IDESC  = (8u << 24) | (8u << 17)  | (1u << 10) | (1u << 7) | (1u << 4); // M128 N64

#if HAS_TCGEN05
__device__ __forceinline__ void mma_bf16_ss(uint32_t d_tmem, uint64_t a_desc, uint64_t b_desc,
                                            uint32_t idesc, bool acc) {
    uint32_t en = acc ? 1u : 0u;
    asm volatile(
        "{\n\t.reg .pred p;\n\tsetp.ne.u32 p, %5, 0;\n\t"
        "tcgen05.mma.cta_group::1.kind::f16 [%0], %1, %2, %3, {%4, %4, %4, %4}, p;\n\t}"
        :: "r"(d_tmem), "l"(a_desc), "l"(b_desc), "r"(idesc), "r"(0u), "r"(en) : "memory");
}
#endif

__device__ __forceinline__ uint32_t pk2(float a, float b) {
    __nv_bfloat162 t = __floats2bfloat162_rn(a, b);
    return *reinterpret_cast<uint32_t*>(&t);
}
__device__ __forceinline__ float bfi(float v) {
    return __bfloat162float(__float2bfloat16(v));
}
__device__ __forceinline__ float ex2f(float x) {
    float r;
    asm("ex2.approx.ftz.f32 %0, %1;" : "=f"(r) : "f"(x));
    return r;
}

// ---------------------------------------------------------------------------
// Merged prep kernel
// ---------------------------------------------------------------------------
__global__ __launch_bounds__(256) void prep_kernel(
    const float* __restrict__ x,
    const float* __restrict__ Wq, const float* __restrict__ Wk,
    const float* __restrict__ Wv, const float* __restrict__ Wo,
    __nv_bfloat16* __restrict__ xhi, __nv_bfloat16* __restrict__ xlo,
    __nv_bfloat16* __restrict__ whi, __nv_bfloat16* __restrict__ wlo)
{
    const int tid = threadIdx.x;
    if (blockIdx.x < 4096) {
        int i = blockIdx.x * 256 + tid;
        float4 v = reinterpret_cast<const float4*>(x)[i];
        float h0 = bfi(v.x), h1 = bfi(v.y), h2 = bfi(v.z), h3 = bfi(v.w);
        reinterpret_cast<uint2*>(xhi)[i] = make_uint2(pk2(v.x, v.y), pk2(v.z, v.w));
        reinterpret_cast<uint2*>(xlo)[i] = make_uint2(pk2(v.x - h0, v.y - h1), pk2(v.z - h2, v.w - h3));
    } else {
        __shared__ float ts[32][33];
        int bid = blockIdx.x - 4096;
        int z = bid >> 10;
        int rem = bid & 1023;
        int n0 = (rem & 31) * 32, k0 = (rem >> 5) * 32;
        const float* W = (z == 0) ? Wq : (z == 1) ? Wk : (z == 2) ? Wv : Wo;
        int tx = tid & 31, ty = tid >> 5;
        for (int r = ty; r < 32; r += 8)
            ts[r][tx] = W[(size_t)(k0 + r) * ED + n0 + tx];
        __syncthreads();
        size_t zoff = (size_t)z * ED * ED;
        for (int r = ty; r < 32; r += 8) {
            float v = ts[tx][r];
            float hf = bfi(v);
            size_t o = zoff + (size_t)(n0 + r) * ED + k0 + tx;
            whi[o] = __float2bfloat16(v);
            wlo[o] = __float2bfloat16(v - hf);
        }
    }
}

// ---------------------------------------------------------------------------
// bf16x3 tcgen05 GEMM — round-10 config (K-tile 64, single buffer, occ 2,
// hoisted cp.async addressing, 8-warp epilogue). Q scale now includes log2e.
// ---------------------------------------------------------------------------
#define GEMM_SMEM (1024 + 65536)

__global__ __launch_bounds__(256, 2) void gemm_bf16x3(
    const __nv_bfloat16* __restrict__ Ahi, const __nv_bfloat16* __restrict__ Alo,
    const __nv_bfloat16* __restrict__ Wh,  const __nv_bfloat16* __restrict__ Wl,
    const float* __restrict__ b0, const float* __restrict__ b1, const float* __restrict__ b2,
    float* __restrict__ cf, __nv_bfloat16* __restrict__ chi, __nv_bfloat16* __restrict__ clo,
    int mode)
{
    extern __shared__ char smc[];
    const int tid = threadIdx.x;
    const int wid = tid >> 5, lid = tid & 31;
    const int cRow = blockIdx.y;
    const int z    = mode ? (blockIdx.x >> 3) : 0;
    const int ncol = mode ? (blockIdx.x & 7) : blockIdx.x;

    const __nv_bfloat16* gA0 = Ahi + (size_t)cRow * 128 * ED;
    const __nv_bfloat16* gA1 = Alo + (size_t)cRow * 128 * ED;
    const __nv_bfloat16* gB0 = Wh + ((size_t)z * ED + ncol * 128) * ED;
    const __nv_bfloat16* gB1 = Wl + ((size_t)z * ED + ncol * 128) * ED;
    const float* bias = mode ? ((z == 0) ? b0 : (z == 1) ? b1 : b2) : b0;

#if HAS_TCGEN05
    const uint32_t smu = smem_to_u32(smc);
    const uint32_t bufu = smu + 1024;

    if (tid == 0) MBARRIER_INIT(smu + 8, 1);
    if (wid == 0) { TCGEN05_ALLOC(smu, 128); TCGEN05_RELINQ(); }
    __syncthreads();
    uint32_t tmem;
    asm volatile("ld.shared.b32 %0, [%1];" : "=r"(tmem) : "r"(smu));

    const int cc = tid & 7;
    const int rb = tid >> 3;
    uint32_t dstj[4];
#pragma unroll
    for (int j = 0; j < 4; j++) {
        uint32_t off = (j * 32 + rb) * 128 + cc * 16;
        dstj[j] = bufu + (off ^ ((off >> 3) & 0x70));
    }
    const __nv_bfloat16* a0p = gA0 + (size_t)rb * ED + cc * 8;
    const __nv_bfloat16* a1p = gA1 + (size_t)rb * ED + cc * 8;
    const __nv_bfloat16* b0p = gB0 + (size_t)rb * ED + cc * 8;
    const __nv_bfloat16* b1p = gB1 + (size_t)rb * ED + cc * 8;

    auto load_tile = [&](int k0e) {
#pragma unroll
        for (int j = 0; j < 4; j++) CP_ASYNC16(dstj[j],          a0p + k0e + j * (32 * ED));
#pragma unroll
        for (int j = 0; j < 4; j++) CP_ASYNC16(dstj[j] + 16384,  a1p + k0e + j * (32 * ED));
#pragma unroll
        for (int j = 0; j < 4; j++) CP_ASYNC16(dstj[j] + 32768,  b0p + k0e + j * (32 * ED));
#pragma unroll
        for (int j = 0; j < 4; j++) CP_ASYNC16(dstj[j] + 49152,  b1p + k0e + j * (32 * ED));
        CP_ASYNC_COMMIT();
    };

    load_tile(0);

    int ph = 0;
#pragma unroll 1
    for (int t = 0; t < 16; t++) {
        CP_ASYNC_WAIT0();
        FENCE_PROXY_ASYNC();
        __syncthreads();

        if (wid == 0) {
            if (elect_one_pred()) {
                uint64_t dAh = MAKE_SMEM_DESC(bufu);
                uint64_t dAl = MAKE_SMEM_DESC(bufu + 16384);
                uint64_t dBh = MAKE_SMEM_DESC(bufu + 32768);
                uint64_t dBl = MAKE_SMEM_DESC(bufu + 49152);
#pragma unroll
                for (int ks = 0; ks < 4; ks++) {
                    mma_bf16_ss(tmem, dAh + ks * 2, dBh + ks * 2, GEMM_IDESC, !(t == 0 && ks == 0));
                    mma_bf16_ss(tmem, dAh + ks * 2, dBl + ks * 2, GEMM_IDESC, true);
                    mma_bf16_ss(tmem, dAl + ks * 2, dBh + ks * 2, GEMM_IDESC, true);
                }
                TCGEN05_COMMIT(smu + 8);
            }
        }
        MBARRIER_WAIT_PARITY(smu + 8, ph); ph ^= 1;
        if (t + 1 < 16) load_tile((t + 1) * 64);
    }
    TCGEN05_FENCE_AFTER();

    // 8-warp epilogue
    {
        const int sub = wid & 3;
        float* wsm = reinterpret_cast<float*>(smc + 1024) + wid * (32 * 33);
#pragma unroll 1
        for (int cc2 = 0; cc2 < 2; cc2++) {
            const int c = (wid >> 2) * 2 + cc2;
            uint32_t regs[32];
            TCGEN05_LD_X32(regs, tmem + c * 32);
            TCGEN05_WAIT_LD();
#pragma unroll
            for (int j = 0; j < 32; j++)
                wsm[lid * 33 + j] = __uint_as_float(regs[j]) + bias[ncol * 128 + c * 32 + j];
            __syncwarp();
            if (mode == 0) {
#pragma unroll
                for (int j = 0; j < 32; j++) {
                    int row = cRow * 128 + sub * 32 + j;
                    int col = ncol * 128 + c * 32 + lid;
                    cf[(size_t)row * ED + col] = wsm[j * 33 + lid];
                }
            } else if (z < 2) {
#pragma unroll
                for (int j = 0; j < 32; j++) {
                    float v = wsm[j * 33 + lid];
                    if (z == 0) v *= 0.18033688f;   // (1/8) * log2(e)
                    int row = cRow * 128 + sub * 32 + j;
                    int col = ncol * 128 + c * 32 + lid;
                    int bb = row >> 11, s = row & 2047;
                    int hh = col >> 6, d = col & 63;
                    float hf = bfi(v);
                    size_t idx = (size_t)z * MROWS * ED + (((size_t)(bb * NH + hh)) * S_LEN + s) * HD + d;
                    chi[idx] = __float2bfloat16(v);
                    clo[idx] = __float2bfloat16(v - hf);
                }
            } else {
#pragma unroll
                for (int j = 0; j < 32; j++) {
                    float v = wsm[lid * 33 + j];
                    int row = cRow * 128 + sub * 32 + lid;
                    int col = ncol * 128 + c * 32 + j;
                    int bb = row >> 11, s = row & 2047;
                    int hh = col >> 6, d = col & 63;
                    float hf = bfi(v);
                    size_t idx = (size_t)2 * MROWS * ED + (((size_t)(bb * NH + hh)) * HD + d) * S_LEN + s;
                    chi[idx] = __float2bfloat16(v);
                    clo[idx] = __float2bfloat16(v - hf);
                }
            }
            __syncwarp();
        }
    }
    __syncthreads();
    if (wid == 0) TCGEN05_DEALLOC(tmem, 128);
#else
    // ---------------- FFMA fallback (never selected on GB300) ----------------
    float* As = reinterpret_cast<float*>(smc);
    float* Bs = As + 16 * 132;
    const int threadRow = tid / 16;
    const int threadCol = tid % 16;

    float acc[8][8];
#pragma unroll
    for (int i = 0; i < 8; i++)
#pragma unroll
        for (int j = 0; j < 8; j++) acc[i][j] = 0.0f;

    for (int k0 = 0; k0 < ED; k0 += 16) {
        for (int i = tid; i < 2048; i += 256) {
            int r = i >> 4, kk = i & 15;
            As[kk * 132 + r] = __bfloat162float(gA0[(size_t)r * ED + k0 + kk]) +
                               __bfloat162float(gA1[(size_t)r * ED + k0 + kk]);
            Bs[kk * 132 + r] = __bfloat162float(gB0[(size_t)r * ED + k0 + kk]) +
                               __bfloat162float(gB1[(size_t)r * ED + k0 + kk]);
        }
        __syncthreads();
#pragma unroll
        for (int kk = 0; kk < 16; kk++) {
            float regM[8], regN[8];
#pragma unroll
            for (int i = 0; i < 8; i++) regM[i] = As[kk * 132 + threadRow * 8 + i];
#pragma unroll
            for (int j = 0; j < 8; j++) regN[j] = Bs[kk * 132 + threadCol * 8 + j];
#pragma unroll
            for (int i = 0; i < 8; i++)
#pragma unroll
                for (int j = 0; j < 8; j++)
                    acc[i][j] = fmaf(regM[i], regN[j], acc[i][j]);
        }
        __syncthreads();
    }

#pragma unroll
    for (int i = 0; i < 8; i++) {
        int row = cRow * 128 + threadRow * 8 + i;
#pragma unroll
        for (int j = 0; j < 8; j++) {
            int col = ncol * 128 + threadCol * 8 + j;
            float v = acc[i][j] + bias[col];
            if (mode == 0) {
                cf[(size_t)row * ED + col] = v;
            } else {
                int bb = row >> 11, s = row & 2047;
                int hh = col >> 6, d = col & 63;
                if (z == 0) v *= 0.18033688f;
                size_t idx;
                if (z < 2) idx = (size_t)z * MROWS * ED + (((size_t)(bb * NH + hh)) * S_LEN + s) * HD + d;
                else       idx = (size_t)2 * MROWS * ED + (((size_t)(bb * NH + hh)) * HD + d) * S_LEN + s;
                float hf = bfi(v);
                chi[idx] = __float2bfloat16(v);
                clo[idx] = __float2bfloat16(v - hf);
            }
        }
    }
#endif
}

// ---------------------------------------------------------------------------
// Banded flash attention on tcgen05 — single-wait pipelined schedule.
// Per tile: wait(mbarS) [implies S(t) & PV(t-1) done] -> issue K(t+1)/V(t)
// loads -> fold PV(t-1) -> LDTM S(t) -> softmax(ex2) -> pack P -> one
// wait_cp+fence+sync -> issue S(t+1) then PV(t), single commit.
// TMEM (alloc 256): S ping-pong at cols 0 / 64, PV at 128-191.
// smem map unchanged (97 KB, occ 2).
// ---------------------------------------------------------------------------
#define ATT_SMEM 99328

__global__ __launch_bounds__(128, 2) void attn_tc_kernel(
    const __nv_bfloat16* __restrict__ qkvh, const __nv_bfloat16* __restrict__ qkvl,
    __nv_bfloat16* __restrict__ Ohi, __nv_bfloat16* __restrict__ Olo)
{
    extern __shared__ char smc[];
    const int tid = threadIdx.x;
    const int wid = tid >> 5, lid = tid & 31;
    const int b = blockIdx.z, h = blockIdx.y;
    const int q0 = blockIdx.x * 128;
    const size_t bh = (size_t)(b * NH + h);

    const __nv_bfloat16* Qh = qkvh + bh * S_LEN * HD;
    const __nv_bfloat16* Ql = qkvl + bh * S_LEN * HD;
    const __nv_bfloat16* Kh = qkvh + (size_t)MROWS * ED + bh * S_LEN * HD;
    const __nv_bfloat16* Kl = qkvl + (size_t)MROWS * ED + bh * S_LEN * HD;
    const __nv_bfloat16* Vh = qkvh + (size_t)2 * MROWS * ED + bh * HD * S_LEN;
    const __nv_bfloat16* Vl = qkvl + (size_t)2 * MROWS * ED + bh * HD * S_LEN;

    const int gq = q0 + wid * 32 + lid;

#if HAS_TCGEN05
    const uint32_t smu = smem_to_u32(smc);

    if (tid == 0) MBARRIER_INIT(smu + 8, 1);
    if (wid == 0) { TCGEN05_ALLOC(smu, 256); TCGEN05_RELINQ(); }
    __syncthreads();
    uint32_t tmem;
    asm volatile("ld.shared.b32 %0, [%1];" : "=r"(tmem) : "r"(smu));

    // Load Q hi/lo (128 rows x 64 bf16, SW128)
#pragma unroll
    for (int i = 0; i < 16; i++) {
        int idx = i * 128 + tid;
        int arr = idx >> 10;
        int r = (idx >> 3) & 127, c = idx & 7;
        const __nv_bfloat16* src = arr ? Ql : Qh;
        uint32_t off = r * 128 + c * 16;
        CP_ASYNC16(smu + 1024 + arr * 16384 + (off ^ ((off >> 3) & 0x70)),
                   src + (size_t)(q0 + r) * HD + c * 8);
    }

    const int it0 = (q0 < 256) ? ((256 - q0) >> 6) : 0;
    const int it1raw = (2240 - q0) >> 6;
    const int it1 = it1raw < 9 ? it1raw : 9;
    const uint32_t kb = smu + 33792;

    const int cc = tid & 7;
    const int rb = tid >> 3;
    uint32_t dstj[4];
#pragma unroll
    for (int j = 0; j < 4; j++) {
        uint32_t off = (j * 16 + rb) * 128 + cc * 16;
        dstj[j] = kb + (off ^ ((off >> 3) & 0x70));
    }
    const __nv_bfloat16* khp = Kh + (size_t)rb * HD + cc * 8;
    const __nv_bfloat16* klp = Kl + (size_t)rb * HD + cc * 8;
    const __nv_bfloat16* vhp = Vh + (size_t)rb * S_LEN + cc * 8;
    const __nv_bfloat16* vlp = Vl + (size_t)rb * S_LEN + cc * 8;

    auto load_k = [&](int ks0) {     // no commit (caller commits group)
        const __nv_bfloat16* kh = khp + (size_t)ks0 * HD;
        const __nv_bfloat16* kl = klp + (size_t)ks0 * HD;
#pragma unroll
        for (int j = 0; j < 4; j++) CP_ASYNC16(dstj[j],          kh + j * (16 * HD));
#pragma unroll
        for (int j = 0; j < 4; j++) CP_ASYNC16(dstj[j] + 8192,   kl + j * (16 * HD));
    };
    auto load_v = [&](int ks0) {
        const __nv_bfloat16* vh = vhp + ks0;
        const __nv_bfloat16* vl = vlp + ks0;
#pragma unroll
        for (int j = 0; j < 4; j++) CP_ASYNC16(dstj[j] + 16384,  vh + j * (16 * S_LEN));
#pragma unroll
        for (int j = 0; j < 4; j++) CP_ASYNC16(dstj[j] + 24576,  vl + j * (16 * S_LEN));
    };

    // Prologue: Q + K(it0), then commit S(it0) into scol 0/1 per parity of it0.
    load_k(q0 - 256 + it0 * 64);
    CP_ASYNC_COMMIT();
    CP_ASYNC_WAIT0();
    FENCE_PROXY_ASYNC();
    __syncthreads();
    if (wid == 0) {
        if (elect_one_pred()) {
            uint64_t dQh = MAKE_SMEM_DESC(smu + 1024);
            uint64_t dQl = MAKE_SMEM_DESC(smu + 1024 + 16384);
            uint64_t dKh = MAKE_SMEM_DESC(kb);
            uint64_t dKl = MAKE_SMEM_DESC(kb + 8192);
            uint32_t sc = tmem + ((it0 & 1) << 6);
#pragma unroll
            for (int ks = 0; ks < 4; ks++) {
                mma_bf16_ss(sc, dQh + ks * 2, dKh + ks * 2, ATT_IDESC, ks > 0);
                mma_bf16_ss(sc, dQh + ks * 2, dKl + ks * 2, ATT_IDESC, true);
                mma_bf16_ss(sc, dQl + ks * 2, dKh + ks * 2, ATT_IDESC, true);
            }
            TCGEN05_COMMIT(smu + 8);
        }
    }

    float o[64];
#pragma unroll
    for (int j = 0; j < 64; j++) o[j] = 0.0f;
    float m = -1e30f, l = 0.0f;
    float prev_corr = 1.0f;
    int ph = 0;

#pragma unroll 1
    for (int t = it0; t <= it1; t++) {
        const int ks0 = q0 - 256 + t * 64;

        // wait: S(t) done (and PV(t-1) done — committed earlier in queue)
        MBARRIER_WAIT_PARITY(smu + 8, ph); ph ^= 1;
        TCGEN05_FENCE_AFTER();

        // issue loads: K(t+1) (K buffer free after S(t)), V(t) (V slot free
        // after PV(t-1)); both complete before the sync below.
        if (t < it1) load_k(ks0 + 64);
        load_v(ks0);
        CP_ASYNC_COMMIT();

        // fold PV(t-1) from TMEM cols 128-191
        if (t > it0) {
            float pv[32];
            TCGEN05_LD_X32(reinterpret_cast<uint32_t*>(pv), tmem + 128);
            TCGEN05_WAIT_LD();
#pragma unroll
            for (int j = 0; j < 32; j++) o[j] = o[j] * prev_corr + pv[j];
            TCGEN05_LD_X32(reinterpret_cast<uint32_t*>(pv), tmem + 160);
            TCGEN05_WAIT_LD();
#pragma unroll
            for (int j = 0; j < 32; j++) o[32 + j] = o[32 + j] * prev_corr + pv[j];
        }

        // LDTM S(t) + softmax (log2 domain: scores pre-scaled by log2e)
        float s[64];
        {
            uint32_t sc = tmem + ((t & 1) << 6);
            TCGEN05_LD_X32(reinterpret_cast<uint32_t*>(s), sc);
            TCGEN05_LD_X32(reinterpret_cast<uint32_t*>(s) + 32, sc + 32);
            TCGEN05_WAIT_LD();
        }

        const bool interior = (ks0 >= gq - HALF_W) && (ks0 + 63 <= gq + HALF_W);
        float mnew, corr, rs = 0.0f;
        if (interior) {
            float tmax = s[0];
#pragma unroll
            for (int j = 1; j < 64; j++) tmax = fmaxf(tmax, s[j]);
            mnew = fmaxf(m, tmax);
            corr = ex2f(m - mnew);
#pragma unroll
            for (int j = 0; j < 64; j++) {
                float p = ex2f(s[j] - mnew);
                s[j] = p;
                rs += p;
            }
        } else {
            float tmax = -1e30f;
#pragma unroll
            for (int j = 0; j < 64; j++) {
                int dk = ks0 + j - gq;
                bool ok = (dk >= -HALF_W) && (dk <= HALF_W);
                s[j] = ok ? s[j] : -1e30f;
                tmax = fmaxf(tmax, s[j]);
            }
            mnew = fmaxf(m, tmax);
            corr = ex2f(m - mnew);
#pragma unroll
            for (int j = 0; j < 64; j++) {
                float p = (s[j] > -1e29f) ? ex2f(s[j] - mnew) : 0.0f;
                s[j] = p;
                rs += p;
            }
        }
        l = l * corr + rs;
        m = mnew;
        prev_corr = corr;

        // pack P -> bf16 hi/lo (P buffer free: PV(t-1) done)
        {
            const int row = wid * 32 + lid;
#pragma unroll
            for (int c8 = 0; c8 < 8; c8++) {
                float v0 = s[c8 * 8 + 0], v1 = s[c8 * 8 + 1], v2 = s[c8 * 8 + 2], v3 = s[c8 * 8 + 3];
                float v4 = s[c8 * 8 + 4], v5 = s[c8 * 8 + 5], v6 = s[c8 * 8 + 6], v7 = s[c8 * 8 + 7];
                uint32_t off = row * 128 + c8 * 16;
                uint32_t sw = off ^ ((off >> 3) & 0x70);
                STS128(smu + 66560 + sw, pk2(v0, v1), pk2(v2, v3), pk2(v4, v5), pk2(v6, v7));
                float h0 = bfi(v0), h1 = bfi(v1), h2 = bfi(v2), h3 = bfi(v3);
                float h4 = bfi(v4), h5 = bfi(v5), h6 = bfi(v6), h7 = bfi(v7);
                STS128(smu + 82944 + sw, pk2(v0 - h0, v1 - h1), pk2(v2 - h2, v3 - h3),
                       pk2(v4 - h4, v5 - h5), pk2(v6 - h6, v7 - h7));
            }
        }

        // one wait/fence/sync covers: K(t+1)+V(t) arrival and P visibility
        CP_ASYNC_WAIT0();
        FENCE_PROXY_ASYNC();
        __syncthreads();

        // issue S(t+1) (overlaps next iter's fold/softmax), then PV(t), commit
        if (wid == 0) {
            if (elect_one_pred()) {
                if (t < it1) {
                    uint64_t dQh = MAKE_SMEM_DESC(smu + 1024);
                    uint64_t dQl = MAKE_SMEM_DESC(smu + 1024 + 16384);
                    uint64_t dKh = MAKE_SMEM_DESC(kb);
                    uint64_t dKl = MAKE_SMEM_DESC(kb + 8192);
                    uint32_t sc = tmem + (((t + 1) & 1) << 6);
#pragma unroll
                    for (int ks = 0; ks < 4; ks++) {
                        mma_bf16_ss(sc, dQh + ks * 2, dKh + ks * 2, ATT_IDESC, ks > 0);
                        mma_bf16_ss(sc, dQh + ks * 2, dKl + ks * 2, ATT_IDESC, true);
                        mma_bf16_ss(sc, dQl + ks * 2, dKh + ks * 2, ATT_IDESC, true);
                    }
                }
                uint64_t dPh = MAKE_SMEM_DESC(smu + 66560);
                uint64_t dPl = MAKE_SMEM_DESC(smu + 82944);
                uint64_t dVh = MAKE_SMEM_DESC(kb + 16384);
                uint64_t dVl = MAKE_SMEM_DESC(kb + 24576);
#pragma unroll
                for (int ks = 0; ks < 4; ks++) {
                    mma_bf16_ss(tmem + 128, dPh + ks * 2, dVh + ks * 2, ATT_IDESC, ks > 0);
                    mma_bf16_ss(tmem + 128, dPh + ks * 2, dVl + ks * 2, ATT_IDESC, true);
                    mma_bf16_ss(tmem + 128, dPl + ks * 2, dVh + ks * 2, ATT_IDESC, true);
                }
                TCGEN05_COMMIT(smu + 8);
            }
        }
    }

    // final: wait for PV(it1), fold, normalize, store
    MBARRIER_WAIT_PARITY(smu + 8, ph);
    TCGEN05_FENCE_AFTER();
    {
        float pv[32];
        TCGEN05_LD_X32(reinterpret_cast<uint32_t*>(pv), tmem + 128);
        TCGEN05_WAIT_LD();
#pragma unroll
        for (int j = 0; j < 32; j++) o[j] = o[j] * prev_corr + pv[j];
        TCGEN05_LD_X32(reinterpret_cast<uint32_t*>(pv), tmem + 160);
        TCGEN05_WAIT_LD();
#pragma unroll
        for (int j = 0; j < 32; j++) o[32 + j] = o[32 + j] * prev_corr + pv[j];
    }

    {
        float inv = 1.0f / l;
        size_t ob = ((size_t)b * S_LEN + gq) * ED + h * HD;
#pragma unroll
        for (int c8 = 0; c8 < 8; c8++) {
            float v0 = o[c8 * 8 + 0] * inv, v1 = o[c8 * 8 + 1] * inv;
            float v2 = o[c8 * 8 + 2] * inv, v3 = o[c8 * 8 + 3] * inv;
            float v4 = o[c8 * 8 + 4] * inv, v5 = o[c8 * 8 + 5] * inv;
            float v6 = o[c8 * 8 + 6] * inv, v7 = o[c8 * 8 + 7] * inv;
            uint4 H = make_uint4(pk2(v0, v1), pk2(v2, v3), pk2(v4, v5), pk2(v6, v7));
            float h0 = bfi(v0), h1 = bfi(v1), h2 = bfi(v2), h3 = bfi(v3);
            float h4 = bfi(v4), h5 = bfi(v5), h6 = bfi(v6), h7 = bfi(v7);
            uint4 L = make_uint4(pk2(v0 - h0, v1 - h1), pk2(v2 - h2, v3 - h3),
                                 pk2(v4 - h4, v5 - h5), pk2(v6 - h6, v7 - h7));
            *reinterpret_cast<uint4*>(Ohi + ob + c8 * 8) = H;
            *reinterpret_cast<uint4*>(Olo + ob + c8 * 8) = L;
        }
    }
    __syncthreads();
    if (wid == 0) TCGEN05_DEALLOC(tmem, 256);
#else
    // ---------------- naive fallback (never selected on GB300) ----------------
    (void)smc;
    const int row = gq;
    float o[64];
#pragma unroll
    for (int j = 0; j < 64; j++) o[j] = 0.0f;
    float mm = -1e30f, ll = 0.0f;
    int k0 = row - HALF_W < 0 ? 0 : row - HALF_W;
    int k1 = row + HALF_W > S_LEN - 1 ? S_LEN - 1 : row + HALF_W;
    for (int gk = k0; gk <= k1; gk++) {
        float sc = 0.0f;
        for (int d = 0; d < 64; d++)
            sc += (__bfloat162float(Qh[(size_t)row * HD + d]) + __bfloat162float(Ql[(size_t)row * HD + d])) *
                  (__bfloat162float(Kh[(size_t)gk * HD + d]) + __bfloat162float(Kl[(size_t)gk * HD + d]));
        float mn = fmaxf(mm, sc);
        float corr = exp2f(mm - mn);
        float p = exp2f(sc - mn);
        ll = ll * corr + p;
        for (int d = 0; d < 64; d++)
            o[d] = o[d] * corr + p * (__bfloat162float(Vh[(size_t)d * S_LEN + gk]) +
                                      __bfloat162float(Vl[(size_t)d * S_LEN + gk]));
        mm = mn;
    }
    float inv = 1.0f / ll;
    size_t ob = ((size_t)b * S_LEN + row) * ED + h * HD;
    for (int d = 0; d < 64; d++) {
        float v = o[d] * inv;
        float hf = bfi(v);
        Ohi[ob + d] = __float2bfloat16(v);
        Olo[ob + d] = __float2bfloat16(v - hf);
    }
#endif
}

// ---------------------------------------------------------------------------
extern "C" void kernel_launch(void* const* d_in, const int* in_sizes, int n_in,
                              void* d_out, int out_size)
{
    (void)in_sizes; (void)n_in; (void)out_size;
    const float* x  = (const float*)d_in[0];
    const float* Wq = (const float*)d_in[1];
    const float* bq = (const float*)d_in[2];
    const float* Wk = (const float*)d_in[3];
    const float* bk = (const float*)d_in[4];
    const float* Wv = (const float*)d_in[5];
    const float* bv = (const float*)d_in[6];
    const float* Wo = (const float*)d_in[7];
    const float* bo = (const float*)d_in[8];

    __nv_bfloat16 *xhi, *xlo, *whi, *wlo, *qkvh, *qkvl, *ahi, *alo;
    cudaGetSymbolAddress((void**)&xhi, g_xhi);
    cudaGetSymbolAddress((void**)&xlo, g_xlo);
    cudaGetSymbolAddress((void**)&whi, g_whi);
    cudaGetSymbolAddress((void**)&wlo, g_wlo);
    cudaGetSymbolAddress((void**)&qkvh, g_qkvh);
    cudaGetSymbolAddress((void**)&qkvl, g_qkvl);
    cudaGetSymbolAddress((void**)&ahi, g_ahi);
    cudaGetSymbolAddress((void**)&alo, g_alo);

    cudaFuncSetAttribute(gemm_bf16x3, cudaFuncAttributeMaxDynamicSharedMemorySize, GEMM_SMEM);
    cudaFuncSetAttribute(attn_tc_kernel, cudaFuncAttributeMaxDynamicSharedMemorySize, ATT_SMEM);

    prep_kernel<<<8192, 256>>>(x, Wq, Wk, Wv, Wo, xhi, xlo, whi, wlo);

    gemm_bf16x3<<<dim3(24, 32), 256, GEMM_SMEM>>>(xhi, xlo, whi, wlo,
                                                  bq, bk, bv, nullptr, qkvh, qkvl, 1);

    attn_tc_kernel<<<dim3(S_LEN / 128, NH, BATCH), 128, ATT_SMEM>>>(qkvh, qkvl, ahi, alo);

    gemm_bf16x3<<<dim3(8, 32), 256, GEMM_SMEM>>>(ahi, alo,
                                                 whi + (size_t)3 * ED * ED, wlo + (size_t)3 * ED * ED,
                                                 bo, bo, bo, (float*)d_out, nullptr, nullptr, 0);
}

// round 14
// speedup vs baseline: 1.2613x; 1.0596x over previous
#include <cuda_runtime.h>
#include <cuda_bf16.h>
#include <cstdint>

#define BATCH 2
#define S_LEN 2048
#define ED    1024
#define NH    16
#define HD    64
#define HALF_W 256
#define MROWS (BATCH * S_LEN)   // 4096

#if defined(__CUDA_ARCH_FEAT_SM103_ALL) || defined(__CUDA_ARCH_FEAT_SM100_ALL)
#define HAS_TCGEN05 1
#else
#define HAS_TCGEN05 0
#endif

// ---------------------------------------------------------------------------
// Scratch (device globals)
// ---------------------------------------------------------------------------
__device__ __nv_bfloat16 g_xhi[MROWS * ED];
__device__ __nv_bfloat16 g_xlo[MROWS * ED];
__device__ __nv_bfloat16 g_whi[4 * ED * ED];   // transposed weights [z][n][k]
__device__ __nv_bfloat16 g_wlo[4 * ED * ED];
__device__ __nv_bfloat16 g_qkvh[3 * MROWS * ED];  // Q,K: [b,h,s,d]; V: [b,h,d,s]
__device__ __nv_bfloat16 g_qkvl[3 * MROWS * ED];
__device__ __nv_bfloat16 g_ahi[MROWS * ED];
__device__ __nv_bfloat16 g_alo[MROWS * ED];

// ---------------------------------------------------------------------------
// PTX helpers
// ---------------------------------------------------------------------------
__device__ __forceinline__ uint32_t smem_to_u32(const void* p) {
    uint32_t a;
    asm("{ .reg .u64 t; cvta.to.shared.u64 t, %1; cvt.u32.u64 %0, t; }" : "=r"(a) : "l"(p));
    return a;
}
#if HAS_TCGEN05
__device__ __forceinline__ uint32_t elect_one_pred() {
    uint32_t pred;
    asm volatile("{\n\t.reg .pred p;\n\telect.sync _|p, 0xFFFFFFFF;\n\tselp.b32 %0, 1, 0, p;\n\t}" : "=r"(pred));
    return pred;
}
#endif
#define MBARRIER_INIT(addr, cnt) \
    asm volatile("mbarrier.init.shared.b64 [%0], %1;" :: "r"((uint32_t)(addr)), "r"((uint32_t)(cnt)) : "memory")
#define MBARRIER_WAIT_PARITY(addr, par) do { \
    uint32_t _m = (uint32_t)(addr); uint32_t _p = (uint32_t)(par); uint32_t _d; \
    asm volatile("{\n\t.reg .pred p;\n\tmbarrier.try_wait.parity.acquire.cta.shared::cta.b64 p, [%1], %2;\n\tselp.b32 %0, 1, 0, p;\n\t}" \
        : "=r"(_d) : "r"(_m), "r"(_p) : "memory"); \
    if (!_d) { \
        asm volatile("{\n\t.reg .pred P1;\n\tWL_%=:\n\tmbarrier.try_wait.parity.acquire.cta.shared::cta.b64 P1, [%0], %1, 0x989680;\n\t@P1 bra.uni WD_%=;\n\tbra.uni WL_%=;\n\tWD_%=:\n\t}" \
            :: "r"(_m), "r"(_p) : "memory"); \
    } } while (0)
#define TCGEN05_ALLOC(sres, nc) \
    asm volatile("tcgen05.alloc.cta_group::1.sync.aligned.shared::cta.b32 [%0], %1;" :: "r"((uint32_t)(sres)), "r"((uint32_t)(nc)) : "memory")
#define TCGEN05_DEALLOC(tm, nc) \
    asm volatile("tcgen05.dealloc.cta_group::1.sync.aligned.b32 %0, %1;" :: "r"(tm), "r"((uint32_t)(nc)))
#define TCGEN05_RELINQ() \
    asm volatile("tcgen05.relinquish_alloc_permit.cta_group::1.sync.aligned;")
#define TCGEN05_COMMIT(mb) \
    asm volatile("tcgen05.commit.cta_group::1.mbarrier::arrive::one.shared::cluster.b64 [%0];" :: "r"((uint32_t)(mb)) : "memory")
#define TCGEN05_FENCE_AFTER() asm volatile("tcgen05.fence::after_thread_sync;" ::: "memory")
#define TCGEN05_WAIT_LD() asm volatile("tcgen05.wait::ld.sync.aligned;" ::: "memory")
#define FENCE_PROXY_ASYNC() asm volatile("fence.proxy.async.shared::cta;" ::: "memory")
#define CP_ASYNC16(saddr, gptr) \
    asm volatile("cp.async.cg.shared.global [%0], [%1], 16;" :: "r"((uint32_t)(saddr)), "l"(gptr) : "memory")
#define CP_ASYNC_COMMIT() asm volatile("cp.async.commit_group;" ::: "memory")
#define CP_ASYNC_WAIT0()  asm volatile("cp.async.wait_group 0;" ::: "memory")
#define STS128(addr, a, b, c, d) \
    asm volatile("st.shared.v4.b32 [%0], {%1, %2, %3, %4};" :: "r"((uint32_t)(addr)), "r"(a), "r"(b), "r"(c), "r"(d) : "memory")

#define TCGEN05_LD_X32(r, ta) \
    asm volatile("tcgen05.ld.sync.aligned.32x32b.x32.b32 " \
        "{%0, %1, %2, %3, %4, %5, %6, %7, %8, %9, %10, %11, %12, %13, %14, %15, " \
        " %16, %17, %18, %19, %20, %21, %22, %23, %24, %25, %26, %27, %28, %29, %30, %31}, [%32];" \
        : "=r"((r)[0]), "=r"((r)[1]), "=r"((r)[2]), "=r"((r)[3]), "=r"((r)[4]), "=r"((r)[5]), "=r"((r)[6]), "=r"((r)[7]), \
          "=r"((r)[8]), "=r"((r)[9]), "=r"((r)[10]), "=r"((r)[11]), "=r"((r)[12]), "=r"((r)[13]), "=r"((r)[14]), "=r"((r)[15]), \
          "=r"((r)[16]), "=r"((r)[17]), "=r"((r)[18]), "=r"((r)[19]), "=r"((r)[20]), "=r"((r)[21]), "=r"((r)[22]), "=r"((r)[23]), \
          "=r"((r)[24]), "=r"((r)[25]), "=r"((r)[26]), "=r"((r)[27]), "=r"((r)[28]), "=r"((r)[29]), "=r"((r)[30]), "=r"((r)[31]) \
        : "r"(ta))

// SMEM descriptor: K-major SW128, LBO=1, SBO=64, version=1
static constexpr uint64_t SMEM_DESC_BASE_SW128 =
    (uint64_t(2) << 61) | (uint64_t(1) << 46) | (uint64_t(64) << 32) | (uint64_t(1) << 16);
#define MAKE_SMEM_DESC(a) (SMEM_DESC_BASE_SW128 | ((uint64_t)((a) >> 4) & 0x3FFF))

// idesc: dtype F32 (bit4), atype BF16 (bit7), btype BF16 (bit10)
static constexpr uint32_t GEMM_IDESC = (8u << 24) | (16u << 17) | (1u << 10) | (1u << 7) | (1u << 4); // M128 N128
static constexpr uint32_t ATT_IDESC  = (8u << 24) | (8u << 17)  | (1u << 10) | (1u << 7) | (1u << 4); // M128 N64

#if HAS_TCGEN05
__device__ __forceinline__ void mma_bf16_ss(uint32_t d_tmem, uint64_t a_desc, uint64_t b_desc,
                                            uint32_t idesc, bool acc) {
    uint32_t en = acc ? 1u : 0u;
    asm volatile(
        "{\n\t.reg .pred p;\n\tsetp.ne.u32 p, %5, 0;\n\t"
        "tcgen05.mma.cta_group::1.kind::f16 [%0], %1, %2, %3, {%4, %4, %4, %4}, p;\n\t}"
        :: "r"(d_tmem), "l"(a_desc), "l"(b_desc), "r"(idesc), "r"(0u), "r"(en) : "memory");
}
#endif

__device__ __forceinline__ uint32_t pk2(float a, float b) {
    __nv_bfloat162 t = __floats2bfloat162_rn(a, b);
    return *reinterpret_cast<uint32_t*>(&t);
}
__device__ __forceinline__ float bfi(float v) {
    return __bfloat162float(__float2bfloat16(v));
}
__device__ __forceinline__ float ex2f(float x) {
    float r;
    asm("ex2.approx.ftz.f32 %0, %1;" : "=f"(r) : "f"(x));
    return r;
}

// ---------------------------------------------------------------------------
// Merged prep kernel
// ---------------------------------------------------------------------------
__global__ __launch_bounds__(256) void prep_kernel(
    const float* __restrict__ x,
    const float* __restrict__ Wq, const float* __restrict__ Wk,
    const float* __restrict__ Wv, const float* __restrict__ Wo,
    __nv_bfloat16* __restrict__ xhi, __nv_bfloat16* __restrict__ xlo,
    __nv_bfloat16* __restrict__ whi, __nv_bfloat16* __restrict__ wlo)
{
    const int tid = threadIdx.x;
    if (blockIdx.x < 4096) {
        int i = blockIdx.x * 256 + tid;
        float4 v = reinterpret_cast<const float4*>(x)[i];
        float h0 = bfi(v.x), h1 = bfi(v.y), h2 = bfi(v.z), h3 = bfi(v.w);
        reinterpret_cast<uint2*>(xhi)[i] = make_uint2(pk2(v.x, v.y), pk2(v.z, v.w));
        reinterpret_cast<uint2*>(xlo)[i] = make_uint2(pk2(v.x - h0, v.y - h1), pk2(v.z - h2, v.w - h3));
    } else {
        __shared__ float ts[32][33];
        int bid = blockIdx.x - 4096;
        int z = bid >> 10;
        int rem = bid & 1023;
        int n0 = (rem & 31) * 32, k0 = (rem >> 5) * 32;
        const float* W = (z == 0) ? Wq : (z == 1) ? Wk : (z == 2) ? Wv : Wo;
        int tx = tid & 31, ty = tid >> 5;
        for (int r = ty; r < 32; r += 8)
            ts[r][tx] = W[(size_t)(k0 + r) * ED + n0 + tx];
        __syncthreads();
        size_t zoff = (size_t)z * ED * ED;
        for (int r = ty; r < 32; r += 8) {
            float v = ts[tx][r];
            float hf = bfi(v);
            size_t o = zoff + (size_t)(n0 + r) * ED + k0 + tx;
            whi[o] = __float2bfloat16(v);
            wlo[o] = __float2bfloat16(v - hf);
        }
    }
}

// ---------------------------------------------------------------------------
// bf16x3 tcgen05 GEMM — K-tile 64, single buffer, hoisted addressing,
// 8-warp epilogue. NOW occupancy 3 (regs capped at 85 via launch_bounds;
// smem 3x66.5 = 199.5 KB <= 227, TMEM 3x128 = 384 <= 512).
// ---------------------------------------------------------------------------
#define GEMM_SMEM (1024 + 65536)

__global__ __launch_bounds__(256, 3) void gemm_bf16x3(
    const __nv_bfloat16* __restrict__ Ahi, const __nv_bfloat16* __restrict__ Alo,
    const __nv_bfloat16* __restrict__ Wh,  const __nv_bfloat16* __restrict__ Wl,
    const float* __restrict__ b0, const float* __restrict__ b1, const float* __restrict__ b2,
    float* __restrict__ cf, __nv_bfloat16* __restrict__ chi, __nv_bfloat16* __restrict__ clo,
    int mode)
{
    extern __shared__ char smc[];
    const int tid = threadIdx.x;
    const int wid = tid >> 5, lid = tid & 31;
    const int cRow = blockIdx.y;
    const int z    = mode ? (blockIdx.x >> 3) : 0;
    const int ncol = mode ? (blockIdx.x & 7) : blockIdx.x;

    const __nv_bfloat16* gA0 = Ahi + (size_t)cRow * 128 * ED;
    const __nv_bfloat16* gA1 = Alo + (size_t)cRow * 128 * ED;
    const __nv_bfloat16* gB0 = Wh + ((size_t)z * ED + ncol * 128) * ED;
    const __nv_bfloat16* gB1 = Wl + ((size_t)z * ED + ncol * 128) * ED;
    const float* bias = mode ? ((z == 0) ? b0 : (z == 1) ? b1 : b2) : b0;

#if HAS_TCGEN05
    const uint32_t smu = smem_to_u32(smc);
    const uint32_t bufu = smu + 1024;

    if (tid == 0) MBARRIER_INIT(smu + 8, 1);
    if (wid == 0) { TCGEN05_ALLOC(smu, 128); TCGEN05_RELINQ(); }
    __syncthreads();
    uint32_t tmem;
    asm volatile("ld.shared.b32 %0, [%1];" : "=r"(tmem) : "r"(smu));

    const int cc = tid & 7;
    const int rb = tid >> 3;
    uint32_t dstj[4];
#pragma unroll
    for (int j = 0; j < 4; j++) {
        uint32_t off = (j * 32 + rb) * 128 + cc * 16;
        dstj[j] = bufu + (off ^ ((off >> 3) & 0x70));
    }
    const __nv_bfloat16* a0p = gA0 + (size_t)rb * ED + cc * 8;
    const __nv_bfloat16* a1p = gA1 + (size_t)rb * ED + cc * 8;
    const __nv_bfloat16* b0p = gB0 + (size_t)rb * ED + cc * 8;
    const __nv_bfloat16* b1p = gB1 + (size_t)rb * ED + cc * 8;

    auto load_tile = [&](int k0e) {
#pragma unroll
        for (int j = 0; j < 4; j++) CP_ASYNC16(dstj[j],          a0p + k0e + j * (32 * ED));
#pragma unroll
        for (int j = 0; j < 4; j++) CP_ASYNC16(dstj[j] + 16384,  a1p + k0e + j * (32 * ED));
#pragma unroll
        for (int j = 0; j < 4; j++) CP_ASYNC16(dstj[j] + 32768,  b0p + k0e + j * (32 * ED));
#pragma unroll
        for (int j = 0; j < 4; j++) CP_ASYNC16(dstj[j] + 49152,  b1p + k0e + j * (32 * ED));
        CP_ASYNC_COMMIT();
    };

    load_tile(0);

    int ph = 0;
#pragma unroll 1
    for (int t = 0; t < 16; t++) {
        CP_ASYNC_WAIT0();
        FENCE_PROXY_ASYNC();
        __syncthreads();

        if (wid == 0) {
            if (elect_one_pred()) {
                uint64_t dAh = MAKE_SMEM_DESC(bufu);
                uint64_t dAl = MAKE_SMEM_DESC(bufu + 16384);
                uint64_t dBh = MAKE_SMEM_DESC(bufu + 32768);
                uint64_t dBl = MAKE_SMEM_DESC(bufu + 49152);
#pragma unroll
                for (int ks = 0; ks < 4; ks++) {
                    mma_bf16_ss(tmem, dAh + ks * 2, dBh + ks * 2, GEMM_IDESC, !(t == 0 && ks == 0));
                    mma_bf16_ss(tmem, dAh + ks * 2, dBl + ks * 2, GEMM_IDESC, true);
                    mma_bf16_ss(tmem, dAl + ks * 2, dBh + ks * 2, GEMM_IDESC, true);
                }
                TCGEN05_COMMIT(smu + 8);
            }
        }
        MBARRIER_WAIT_PARITY(smu + 8, ph); ph ^= 1;
        if (t + 1 < 16) load_tile((t + 1) * 64);
    }
    TCGEN05_FENCE_AFTER();

    // 8-warp epilogue
    {
        const int sub = wid & 3;
        float* wsm = reinterpret_cast<float*>(smc + 1024) + wid * (32 * 33);
#pragma unroll 1
        for (int cc2 = 0; cc2 < 2; cc2++) {
            const int c = (wid >> 2) * 2 + cc2;
            uint32_t regs[32];
            TCGEN05_LD_X32(regs, tmem + c * 32);
            TCGEN05_WAIT_LD();
#pragma unroll
            for (int j = 0; j < 32; j++)
                wsm[lid * 33 + j] = __uint_as_float(regs[j]) + bias[ncol * 128 + c * 32 + j];
            __syncwarp();
            if (mode == 0) {
#pragma unroll
                for (int j = 0; j < 32; j++) {
                    int row = cRow * 128 + sub * 32 + j;
                    int col = ncol * 128 + c * 32 + lid;
                    cf[(size_t)row * ED + col] = wsm[j * 33 + lid];
                }
            } else if (z < 2) {
#pragma unroll
                for (int j = 0; j < 32; j++) {
                    float v = wsm[j * 33 + lid];
                    if (z == 0) v *= 0.18033688f;   // (1/8) * log2(e)
                    int row = cRow * 128 + sub * 32 + j;
                    int col = ncol * 128 + c * 32 + lid;
                    int bb = row >> 11, s = row & 2047;
                    int hh = col >> 6, d = col & 63;
                    float hf = bfi(v);
                    size_t idx = (size_t)z * MROWS * ED + (((size_t)(bb * NH + hh)) * S_LEN + s) * HD + d;
                    chi[idx] = __float2bfloat16(v);
                    clo[idx] = __float2bfloat16(v - hf);
                }
            } else {
#pragma unroll
                for (int j = 0; j < 32; j++) {
                    float v = wsm[lid * 33 + j];
                    int row = cRow * 128 + sub * 32 + lid;
                    int col = ncol * 128 + c * 32 + j;
                    int bb = row >> 11, s = row & 2047;
                    int hh = col >> 6, d = col & 63;
                    float hf = bfi(v);
                    size_t idx = (size_t)2 * MROWS * ED + (((size_t)(bb * NH + hh)) * HD + d) * S_LEN + s;
                    chi[idx] = __float2bfloat16(v);
                    clo[idx] = __float2bfloat16(v - hf);
                }
            }
            __syncwarp();
        }
    }
    __syncthreads();
    if (wid == 0) TCGEN05_DEALLOC(tmem, 128);
#else
    // ---------------- FFMA fallback (never selected on GB300) ----------------
    float* As = reinterpret_cast<float*>(smc);
    float* Bs = As + 16 * 132;
    const int threadRow = tid / 16;
    const int threadCol = tid % 16;

    float acc[8][8];
#pragma unroll
    for (int i = 0; i < 8; i++)
#pragma unroll
        for (int j = 0; j < 8; j++) acc[i][j] = 0.0f;

    for (int k0 = 0; k0 < ED; k0 += 16) {
        for (int i = tid; i < 2048; i += 256) {
            int r = i >> 4, kk = i & 15;
            As[kk * 132 + r] = __bfloat162float(gA0[(size_t)r * ED + k0 + kk]) +
                               __bfloat162float(gA1[(size_t)r * ED + k0 + kk]);
            Bs[kk * 132 + r] = __bfloat162float(gB0[(size_t)r * ED + k0 + kk]) +
                               __bfloat162float(gB1[(size_t)r * ED + k0 + kk]);
        }
        __syncthreads();
#pragma unroll
        for (int kk = 0; kk < 16; kk++) {
            float regM[8], regN[8];
#pragma unroll
            for (int i = 0; i < 8; i++) regM[i] = As[kk * 132 + threadRow * 8 + i];
#pragma unroll
            for (int j = 0; j < 8; j++) regN[j] = Bs[kk * 132 + threadCol * 8 + j];
#pragma unroll
            for (int i = 0; i < 8; i++)
#pragma unroll
                for (int j = 0; j < 8; j++)
                    acc[i][j] = fmaf(regM[i], regN[j], acc[i][j]);
        }
        __syncthreads();
    }

#pragma unroll
    for (int i = 0; i < 8; i++) {
        int row = cRow * 128 + threadRow * 8 + i;
#pragma unroll
        for (int j = 0; j < 8; j++) {
            int col = ncol * 128 + threadCol * 8 + j;
            float v = acc[i][j] + bias[col];
            if (mode == 0) {
                cf[(size_t)row * ED + col] = v;
            } else {
                int bb = row >> 11, s = row & 2047;
                int hh = col >> 6, d = col & 63;
                if (z == 0) v *= 0.18033688f;
                size_t idx;
                if (z < 2) idx = (size_t)z * MROWS * ED + (((size_t)(bb * NH + hh)) * S_LEN + s) * HD + d;
                else       idx = (size_t)2 * MROWS * ED + (((size_t)(bb * NH + hh)) * HD + d) * S_LEN + s;
                float hf = bfi(v);
                chi[idx] = __float2bfloat16(v);
                clo[idx] = __float2bfloat16(v - hf);
            }
        }
    }
#endif
}

// ---------------------------------------------------------------------------
// Banded flash attention on tcgen05 — single-wait pipelined schedule
// (unchanged from round 13).
// ---------------------------------------------------------------------------
#define ATT_SMEM 99328

__global__ __launch_bounds__(128, 2) void attn_tc_kernel(
    const __nv_bfloat16* __restrict__ qkvh, const __nv_bfloat16* __restrict__ qkvl,
    __nv_bfloat16* __restrict__ Ohi, __nv_bfloat16* __restrict__ Olo)
{
    extern __shared__ char smc[];
    const int tid = threadIdx.x;
    const int wid = tid >> 5, lid = tid & 31;
    const int b = blockIdx.z, h = blockIdx.y;
    const int q0 = blockIdx.x * 128;
    const size_t bh = (size_t)(b * NH + h);

    const __nv_bfloat16* Qh = qkvh + bh * S_LEN * HD;
    const __nv_bfloat16* Ql = qkvl + bh * S_LEN * HD;
    const __nv_bfloat16* Kh = qkvh + (size_t)MROWS * ED + bh * S_LEN * HD;
    const __nv_bfloat16* Kl = qkvl + (size_t)MROWS * ED + bh * S_LEN * HD;
    const __nv_bfloat16* Vh = qkvh + (size_t)2 * MROWS * ED + bh * HD * S_LEN;
    const __nv_bfloat16* Vl = qkvl + (size_t)2 * MROWS * ED + bh * HD * S_LEN;

    const int gq = q0 + wid * 32 + lid;

#if HAS_TCGEN05
    const uint32_t smu = smem_to_u32(smc);

    if (tid == 0) MBARRIER_INIT(smu + 8, 1);
    if (wid == 0) { TCGEN05_ALLOC(smu, 256); TCGEN05_RELINQ(); }
    __syncthreads();
    uint32_t tmem;
    asm volatile("ld.shared.b32 %0, [%1];" : "=r"(tmem) : "r"(smu));

    // Load Q hi/lo (128 rows x 64 bf16, SW128)
#pragma unroll
    for (int i = 0; i < 16; i++) {
        int idx = i * 128 + tid;
        int arr = idx >> 10;
        int r = (idx >> 3) & 127, c = idx & 7;
        const __nv_bfloat16* src = arr ? Ql : Qh;
        uint32_t off = r * 128 + c * 16;
        CP_ASYNC16(smu + 1024 + arr * 16384 + (off ^ ((off >> 3) & 0x70)),
                   src + (size_t)(q0 + r) * HD + c * 8);
    }

    const int it0 = (q0 < 256) ? ((256 - q0) >> 6) : 0;
    const int it1raw = (2240 - q0) >> 6;
    const int it1 = it1raw < 9 ? it1raw : 9;
    const uint32_t kb = smu + 33792;

    const int cc = tid & 7;
    const int rb = tid >> 3;
    uint32_t dstj[4];
#pragma unroll
    for (int j = 0; j < 4; j++) {
        uint32_t off = (j * 16 + rb) * 128 + cc * 16;
        dstj[j] = kb + (off ^ ((off >> 3) & 0x70));
    }
    const __nv_bfloat16* khp = Kh + (size_t)rb * HD + cc * 8;
    const __nv_bfloat16* klp = Kl + (size_t)rb * HD + cc * 8;
    const __nv_bfloat16* vhp = Vh + (size_t)rb * S_LEN + cc * 8;
    const __nv_bfloat16* vlp = Vl + (size_t)rb * S_LEN + cc * 8;

    auto load_k = [&](int ks0) {
        const __nv_bfloat16* kh = khp + (size_t)ks0 * HD;
        const __nv_bfloat16* kl = klp + (size_t)ks0 * HD;
#pragma unroll
        for (int j = 0; j < 4; j++) CP_ASYNC16(dstj[j],          kh + j * (16 * HD));
#pragma unroll
        for (int j = 0; j < 4; j++) CP_ASYNC16(dstj[j] + 8192,   kl + j * (16 * HD));
    };
    auto load_v = [&](int ks0) {
        const __nv_bfloat16* vh = vhp + ks0;
        const __nv_bfloat16* vl = vlp + ks0;
#pragma unroll
        for (int j = 0; j < 4; j++) CP_ASYNC16(dstj[j] + 16384,  vh + j * (16 * S_LEN));
#pragma unroll
        for (int j = 0; j < 4; j++) CP_ASYNC16(dstj[j] + 24576,  vl + j * (16 * S_LEN));
    };

    // Prologue: Q + K(it0), then commit S(it0).
    load_k(q0 - 256 + it0 * 64);
    CP_ASYNC_COMMIT();
    CP_ASYNC_WAIT0();
    FENCE_PROXY_ASYNC();
    __syncthreads();
    if (wid == 0) {
        if (elect_one_pred()) {
            uint64_t dQh = MAKE_SMEM_DESC(smu + 1024);
            uint64_t dQl = MAKE_SMEM_DESC(smu + 1024 + 16384);
            uint64_t dKh = MAKE_SMEM_DESC(kb);
            uint64_t dKl = MAKE_SMEM_DESC(kb + 8192);
            uint32_t sc = tmem + ((it0 & 1) << 6);
#pragma unroll
            for (int ks = 0; ks < 4; ks++) {
                mma_bf16_ss(sc, dQh + ks * 2, dKh + ks * 2, ATT_IDESC, ks > 0);
                mma_bf16_ss(sc, dQh + ks * 2, dKl + ks * 2, ATT_IDESC, true);
                mma_bf16_ss(sc, dQl + ks * 2, dKh + ks * 2, ATT_IDESC, true);
            }
            TCGEN05_COMMIT(smu + 8);
        }
    }

    float o[64];
#pragma unroll
    for (int j = 0; j < 64; j++) o[j] = 0.0f;
    float m = -1e30f, l = 0.0f;
    float prev_corr = 1.0f;
    int ph = 0;

#pragma unroll 1
    for (int t = it0; t <= it1; t++) {
        const int ks0 = q0 - 256 + t * 64;

        MBARRIER_WAIT_PARITY(smu + 8, ph); ph ^= 1;
        TCGEN05_FENCE_AFTER();

        if (t < it1) load_k(ks0 + 64);
        load_v(ks0);
        CP_ASYNC_COMMIT();

        // fold PV(t-1) from TMEM cols 128-191
        if (t > it0) {
            float pv[32];
            TCGEN05_LD_X32(reinterpret_cast<uint32_t*>(pv), tmem + 128);
            TCGEN05_WAIT_LD();
#pragma unroll
            for (int j = 0; j < 32; j++) o[j] = o[j] * prev_corr + pv[j];
            TCGEN05_LD_X32(reinterpret_cast<uint32_t*>(pv), tmem + 160);
            TCGEN05_WAIT_LD();
#pragma unroll
            for (int j = 0; j < 32; j++) o[32 + j] = o[32 + j] * prev_corr + pv[j];
        }

        // LDTM S(t) + softmax (log2 domain)
        float s[64];
        {
            uint32_t sc = tmem + ((t & 1) << 6);
            TCGEN05_LD_X32(reinterpret_cast<uint32_t*>(s), sc);
            TCGEN05_LD_X32(reinterpret_cast<uint32_t*>(s) + 32, sc + 32);
            TCGEN05_WAIT_LD();
        }

        const bool interior = (ks0 >= gq - HALF_W) && (ks0 + 63 <= gq + HALF_W);
        float mnew, corr, rs = 0.0f;
        if (interior) {
            float tmax = s[0];
#pragma unroll
            for (int j = 1; j < 64; j++) tmax = fmaxf(tmax, s[j]);
            mnew = fmaxf(m, tmax);
            corr = ex2f(m - mnew);
#pragma unroll
            for (int j = 0; j < 64; j++) {
                float p = ex2f(s[j] - mnew);
                s[j] = p;
                rs += p;
            }
        } else {
            float tmax = -1e30f;
#pragma unroll
            for (int j = 0; j < 64; j++) {
                int dk = ks0 + j - gq;
                bool ok = (dk >= -HALF_W) && (dk <= HALF_W);
                s[j] = ok ? s[j] : -1e30f;
                tmax = fmaxf(tmax, s[j]);
            }
            mnew = fmaxf(m, tmax);
            corr = ex2f(m - mnew);
#pragma unroll
            for (int j = 0; j < 64; j++) {
                float p = (s[j] > -1e29f) ? ex2f(s[j] - mnew) : 0.0f;
                s[j] = p;
                rs += p;
            }
        }
        l = l * corr + rs;
        m = mnew;
        prev_corr = corr;

        // pack P -> bf16 hi/lo
        {
            const int row = wid * 32 + lid;
#pragma unroll
            for (int c8 = 0; c8 < 8; c8++) {
                float v0 = s[c8 * 8 + 0], v1 = s[c8 * 8 + 1], v2 = s[c8 * 8 + 2], v3 = s[c8 * 8 + 3];
                float v4 = s[c8 * 8 + 4], v5 = s[c8 * 8 + 5], v6 = s[c8 * 8 + 6], v7 = s[c8 * 8 + 7];
                uint32_t off = row * 128 + c8 * 16;
                uint32_t sw = off ^ ((off >> 3) & 0x70);
                STS128(smu + 66560 + sw, pk2(v0, v1), pk2(v2, v3), pk2(v4, v5), pk2(v6, v7));
                float h0 = bfi(v0), h1 = bfi(v1), h2 = bfi(v2), h3 = bfi(v3);
                float h4 = bfi(v4), h5 = bfi(v5), h6 = bfi(v6), h7 = bfi(v7);
                STS128(smu + 82944 + sw, pk2(v0 - h0, v1 - h1), pk2(v2 - h2, v3 - h3),
                       pk2(v4 - h4, v5 - h5), pk2(v6 - h6, v7 - h7));
            }
        }

        CP_ASYNC_WAIT0();
        FENCE_PROXY_ASYNC();
        __syncthreads();

        // issue S(t+1) then PV(t), single commit
        if (wid == 0) {
            if (elect_one_pred()) {
                if (t < it1) {
                    uint64_t dQh = MAKE_SMEM_DESC(smu + 1024);
                    uint64_t dQl = MAKE_SMEM_DESC(smu + 1024 + 16384);
                    uint64_t dKh = MAKE_SMEM_DESC(kb);
                    uint64_t dKl = MAKE_SMEM_DESC(kb + 8192);
                    uint32_t sc = tmem + (((t + 1) & 1) << 6);
#pragma unroll
                    for (int ks = 0; ks < 4; ks++) {
                        mma_bf16_ss(sc, dQh + ks * 2, dKh + ks * 2, ATT_IDESC, ks > 0);
                        mma_bf16_ss(sc, dQh + ks * 2, dKl + ks * 2, ATT_IDESC, true);
                        mma_bf16_ss(sc, dQl + ks * 2, dKh + ks * 2, ATT_IDESC, true);
                    }
                }
                uint64_t dPh = MAKE_SMEM_DESC(smu + 66560);
                uint64_t dPl = MAKE_SMEM_DESC(smu + 82944);
                uint64_t dVh = MAKE_SMEM_DESC(kb + 16384);
                uint64_t dVl = MAKE_SMEM_DESC(kb + 24576);
#pragma unroll
                for (int ks = 0; ks < 4; ks++) {
                    mma_bf16_ss(tmem + 128, dPh + ks * 2, dVh + ks * 2, ATT_IDESC, ks > 0);
                    mma_bf16_ss(tmem + 128, dPh + ks * 2, dVl + ks * 2, ATT_IDESC, true);
                    mma_bf16_ss(tmem + 128, dPl + ks * 2, dVh + ks * 2, ATT_IDESC, true);
                }
                TCGEN05_COMMIT(smu + 8);
            }
        }
    }

    // final: wait for PV(it1), fold, normalize, store
    MBARRIER_WAIT_PARITY(smu + 8, ph);
    TCGEN05_FENCE_AFTER();
    {
        float pv[32];
        TCGEN05_LD_X32(reinterpret_cast<uint32_t*>(pv), tmem + 128);
        TCGEN05_WAIT_LD();
#pragma unroll
        for (int j = 0; j < 32; j++) o[j] = o[j] * prev_corr + pv[j];
        TCGEN05_LD_X32(reinterpret_cast<uint32_t*>(pv), tmem + 160);
        TCGEN05_WAIT_LD();
#pragma unroll
        for (int j = 0; j < 32; j++) o[32 + j] = o[32 + j] * prev_corr + pv[j];
    }

    {
        float inv = 1.0f / l;
        size_t ob = ((size_t)b * S_LEN + gq) * ED + h * HD;
#pragma unroll
        for (int c8 = 0; c8 < 8; c8++) {
            float v0 = o[c8 * 8 + 0] * inv, v1 = o[c8 * 8 + 1] * inv;
            float v2 = o[c8 * 8 + 2] * inv, v3 = o[c8 * 8 + 3] * inv;
            float v4 = o[c8 * 8 + 4] * inv, v5 = o[c8 * 8 + 5] * inv;
            float v6 = o[c8 * 8 + 6] * inv, v7 = o[c8 * 8 + 7] * inv;
            uint4 H = make_uint4(pk2(v0, v1), pk2(v2, v3), pk2(v4, v5), pk2(v6, v7));
            float h0 = bfi(v0), h1 = bfi(v1), h2 = bfi(v2), h3 = bfi(v3);
            float h4 = bfi(v4), h5 = bfi(v5), h6 = bfi(v6), h7 = bfi(v7);
            uint4 L = make_uint4(pk2(v0 - h0, v1 - h1), pk2(v2 - h2, v3 - h3),
                                 pk2(v4 - h4, v5 - h5), pk2(v6 - h6, v7 - h7));
            *reinterpret_cast<uint4*>(Ohi + ob + c8 * 8) = H;
            *reinterpret_cast<uint4*>(Olo + ob + c8 * 8) = L;
        }
    }
    __syncthreads();
    if (wid == 0) TCGEN05_DEALLOC(tmem, 256);
#else
    // ---------------- naive fallback (never selected on GB300) ----------------
    (void)smc;
    const int row = gq;
    float o[64];
#pragma unroll
    for (int j = 0; j < 64; j++) o[j] = 0.0f;
    float mm = -1e30f, ll = 0.0f;
    int k0 = row - HALF_W < 0 ? 0 : row - HALF_W;
    int k1 = row + HALF_W > S_LEN - 1 ? S_LEN - 1 : row + HALF_W;
    for (int gk = k0; gk <= k1; gk++) {
        float sc = 0.0f;
        for (int d = 0; d < 64; d++)
            sc += (__bfloat162float(Qh[(size_t)row * HD + d]) + __bfloat162float(Ql[(size_t)row * HD + d])) *
                  (__bfloat162float(Kh[(size_t)gk * HD + d]) + __bfloat162float(Kl[(size_t)gk * HD + d]));
        float mn = fmaxf(mm, sc);
        float corr = exp2f(mm - mn);
        float p = exp2f(sc - mn);
        ll = ll * corr + p;
        for (int d = 0; d < 64; d++)
            o[d] = o[d] * corr + p * (__bfloat162float(Vh[(size_t)d * S_LEN + gk]) +
                                      __bfloat162float(Vl[(size_t)d * S_LEN + gk]));
        mm = mn;
    }
    float inv = 1.0f / ll;
    size_t ob = ((size_t)b * S_LEN + row) * ED + h * HD;
    for (int d = 0; d < 64; d++) {
        float v = o[d] * inv;
        float hf = bfi(v);
        Ohi[ob + d] = __float2bfloat16(v);
        Olo[ob + d] = __float2bfloat16(v - hf);
    }
#endif
}

// ---------------------------------------------------------------------------
extern "C" void kernel_launch(void* const* d_in, const int* in_sizes, int n_in,
                              void* d_out, int out_size)
{
    (void)in_sizes; (void)n_in; (void)out_size;
    const float* x  = (const float*)d_in[0];
    const float* Wq = (const float*)d_in[1];
    const float* bq = (const float*)d_in[2];
    const float* Wk = (const float*)d_in[3];
    const float* bk = (const float*)d_in[4];
    const float* Wv = (const float*)d_in[5];
    const float* bv = (const float*)d_in[6];
    const float* Wo = (const float*)d_in[7];
    const float* bo = (const float*)d_in[8];

    __nv_bfloat16 *xhi, *xlo, *whi, *wlo, *qkvh, *qkvl, *ahi, *alo;
    cudaGetSymbolAddress((void**)&xhi, g_xhi);
    cudaGetSymbolAddress((void**)&xlo, g_xlo);
    cudaGetSymbolAddress((void**)&whi, g_whi);
    cudaGetSymbolAddress((void**)&wlo, g_wlo);
    cudaGetSymbolAddress((void**)&qkvh, g_qkvh);
    cudaGetSymbolAddress((void**)&qkvl, g_qkvl);
    cudaGetSymbolAddress((void**)&ahi, g_ahi);
    cudaGetSymbolAddress((void**)&alo, g_alo);

    cudaFuncSetAttribute(gemm_bf16x3, cudaFuncAttributeMaxDynamicSharedMemorySize, GEMM_SMEM);
    cudaFuncSetAttribute(attn_tc_kernel, cudaFuncAttributeMaxDynamicSharedMemorySize, ATT_SMEM);

    prep_kernel<<<8192, 256>>>(x, Wq, Wk, Wv, Wo, xhi, xlo, whi, wlo);

    gemm_bf16x3<<<dim3(24, 32), 256, GEMM_SMEM>>>(xhi, xlo, whi, wlo,
                                                  bq, bk, bv, nullptr, qkvh, qkvl, 1);

    attn_tc_kernel<<<dim3(S_LEN / 128, NH, BATCH), 128, ATT_SMEM>>>(qkvh, qkvl, ahi, alo);

    gemm_bf16x3<<<dim3(8, 32), 256, GEMM_SMEM>>>(ahi, alo,
                                                 whi + (size_t)3 * ED * ED, wlo + (size_t)3 * ED * ED,
                                                 bo, bo, bo, (float*)d_out, nullptr, nullptr, 0);
}